// round 7
// baseline (speedup 1.0000x reference)
#include <cuda_runtime.h>
#include <cstdint>
#include <math.h>

// ---------------------------------------------------------------------------
// Attention_3856880632117 — mma.sync bf16 3-term split (R3 core, re-tiled).
// ptxas target is plain sm_103 (no 'a'): no tcgen05; tensor via baseline
// mma.sync.m16n8k16.bf16 + ldmatrix. Hot loop: LDG(fp32)->cvt->STS register-
// staged double buffer, ONE __syncthreads per K-chunk (proven fastest core).
// 512 threads/CTA, 4x4 warp grid, 32x32 warp tiles on a 128x128 CTA tile.
//
//   Stage 1: q = x Wq^T, k = x Wk^T, vt = Wv x^T  (vt layout [c][b*T+t])
//   Stage 2: S = q k^T (lower-triangular tiles only), fp32
//   Stage 3: causal softmax — warp-per-row, row in registers, single pass
//   Stage 4: out = P vt^T (k-extent clipped)
// All GEMMs: C = A*B^T, fp32 I/O; C += Ah*Bh + Ah*Bl + Al*Bh (bf16 split).
// ---------------------------------------------------------------------------

#define NB 4
#define NT 2048
#define NCH 1024
#define NXT (NB * NT)      // 8192
#define NTHR 512

// Scratch (allocation-free rule: __device__ globals).
__device__ float g_q [(size_t)NB * NT * NCH];   // 32 MB
__device__ float g_k [(size_t)NB * NT * NCH];   // 32 MB
__device__ float g_vt[(size_t)NCH * NXT];       // 32 MB, [c][b*T + t]
__device__ float g_s [(size_t)NB * NT * NT];    // 64 MB (scores -> probs)

// ---------------- primitives ------------------------------------------------
__device__ __forceinline__ void ldsm4(uint32_t* r, uint32_t addr) {
    asm volatile("ldmatrix.sync.aligned.m8n8.x4.shared.b16 {%0,%1,%2,%3}, [%4];"
                 : "=r"(r[0]), "=r"(r[1]), "=r"(r[2]), "=r"(r[3]) : "r"(addr));
}
__device__ __forceinline__ void mma_bf16(float* c, const uint32_t* a, const uint32_t* b) {
    asm volatile(
        "mma.sync.aligned.m16n8k16.row.col.f32.bf16.bf16.f32 "
        "{%0,%1,%2,%3},{%4,%5,%6,%7},{%8,%9},{%0,%1,%2,%3};"
        : "+f"(c[0]), "+f"(c[1]), "+f"(c[2]), "+f"(c[3])
        : "r"(a[0]), "r"(a[1]), "r"(a[2]), "r"(a[3]), "r"(b[0]), "r"(b[1]));
}
__device__ __forceinline__ uint32_t smem_u32(const void* p) {
    uint32_t a;
    asm("{ .reg .u64 t; cvta.to.shared.u64 t, %1; cvt.u32.u64 %0, t; }"
        : "=r"(a) : "l"(p));
    return a;
}
__device__ __forceinline__ uint32_t pack2(float a, float b) {
    uint32_t r;
    asm("cvt.rn.bf16x2.f32 %0, %1, %2;" : "=r"(r) : "f"(a), "f"(b));
    return r;
}

// ---------------------------------------------------------------------------
// SMEM: per stage, 4 regions (Ah|Al|Bh|Bl), 128 rows x 64B payload, 80B pitch
// (conflict-free ldmatrix). 2 stages, register-staged LDG double buffer.
// ---------------------------------------------------------------------------
#define PITCHB     80
#define REGION     10240
#define STAGE_B    40960
#define SMEM_TOTAL (2 * STAGE_B)

// Core: accumulate 128x128 tile over nch K-chunks of 32 (fp32 inputs,
// in-loop hi/lo split). Warp (wm,wn) owns rows [wm*32,+32), cols [wn*32,+32).
__device__ __forceinline__ void mma_core(
    const float* __restrict__ At, int lda,
    const float* __restrict__ Bt, int ldb,
    int nch, float (&acc)[2][4][4])
{
    extern __shared__ char smraw[];
    char* sm = smraw;
    const uint32_t smu = smem_u32(sm);

    const int tid  = threadIdx.x;
    const int lane = tid & 31;
    const int wid  = tid >> 5;
    const int wm   = wid >> 2;   // 0..3
    const int wn   = wid & 3;    // 0..3

    const uint32_t aRowByte = (uint32_t)(lane & 15) * PITCHB + (uint32_t)(lane >> 4) * 16;
    const uint32_t bRowByte = (uint32_t)(((lane >> 4) << 3) + (lane & 7)) * PITCHB
                            + (uint32_t)((lane >> 3) & 1) * 16;

    float4 pa[2], pb[2];   // register staging: 2 float4 per tensor per chunk

    auto ldg_chunk = [&](int kt) {
        const int kb = kt * 32;
        #pragma unroll
        for (int i = 0; i < 2; ++i) {
            int idx = i * NTHR + tid;
            int r = idx >> 3, c4 = idx & 7;       // r: 0..127, c4: 4-float seg
            pa[i] = *reinterpret_cast<const float4*>(At + (size_t)r * lda + kb + c4 * 4);
            pb[i] = *reinterpret_cast<const float4*>(Bt + (size_t)r * ldb + kb + c4 * 4);
        }
    };

    auto cvt_sts = [&](int buf) {
        char* base = sm + buf * STAGE_B;
        #pragma unroll
        for (int i = 0; i < 2; ++i) {
            int idx = i * NTHR + tid;
            int r = idx >> 3, c4 = idx & 7;
            uint32_t off = (uint32_t)r * PITCHB + (uint32_t)c4 * 8;
            {   // A
                float4 v = pa[i];
                uint32_t h01 = pack2(v.y, v.x);
                uint32_t h23 = pack2(v.w, v.z);
                float hx = __uint_as_float(h01 << 16);
                float hy = __uint_as_float(h01 & 0xFFFF0000u);
                float hz = __uint_as_float(h23 << 16);
                float hw = __uint_as_float(h23 & 0xFFFF0000u);
                *reinterpret_cast<uint2*>(base + off) = make_uint2(h01, h23);
                *reinterpret_cast<uint2*>(base + REGION + off) =
                    make_uint2(pack2(v.y - hy, v.x - hx), pack2(v.w - hw, v.z - hz));
            }
            {   // B
                float4 v = pb[i];
                uint32_t h01 = pack2(v.y, v.x);
                uint32_t h23 = pack2(v.w, v.z);
                float hx = __uint_as_float(h01 << 16);
                float hy = __uint_as_float(h01 & 0xFFFF0000u);
                float hz = __uint_as_float(h23 << 16);
                float hw = __uint_as_float(h23 & 0xFFFF0000u);
                *reinterpret_cast<uint2*>(base + 2 * REGION + off) = make_uint2(h01, h23);
                *reinterpret_cast<uint2*>(base + 3 * REGION + off) =
                    make_uint2(pack2(v.y - hy, v.x - hx), pack2(v.w - hw, v.z - hz));
            }
        }
    };

    auto mma_chunk = [&](int buf) {
        const uint32_t sbase = smu + (uint32_t)buf * STAGE_B;
        #pragma unroll
        for (int sk = 0; sk < 2; ++sk) {
            uint32_t ah[2][4], al[2][4], bh[4][2], bl[4][2];
            const uint32_t aBase = sbase + (uint32_t)(wm * 32) * PITCHB + aRowByte
                                 + (uint32_t)sk * 32;
            #pragma unroll
            for (int mf = 0; mf < 2; ++mf) {
                ldsm4(ah[mf], aBase + (uint32_t)mf * (16 * PITCHB));
                ldsm4(al[mf], aBase + (uint32_t)mf * (16 * PITCHB) + REGION);
            }
            const uint32_t bBase = sbase + 2 * REGION + (uint32_t)(wn * 32) * PITCHB
                                 + bRowByte + (uint32_t)sk * 32;
            #pragma unroll
            for (int p = 0; p < 2; ++p) {
                uint32_t t[4];
                ldsm4(t, bBase + (uint32_t)p * (16 * PITCHB));
                bh[2 * p][0] = t[0]; bh[2 * p][1] = t[1];
                bh[2 * p + 1][0] = t[2]; bh[2 * p + 1][1] = t[3];
                ldsm4(t, bBase + (uint32_t)p * (16 * PITCHB) + REGION);
                bl[2 * p][0] = t[0]; bl[2 * p][1] = t[1];
                bl[2 * p + 1][0] = t[2]; bl[2 * p + 1][1] = t[3];
            }
            #pragma unroll
            for (int mf = 0; mf < 2; ++mf)
                #pragma unroll
                for (int nf = 0; nf < 4; ++nf)
                    mma_bf16(acc[mf][nf], ah[mf], bh[nf]);
            #pragma unroll
            for (int mf = 0; mf < 2; ++mf)
                #pragma unroll
                for (int nf = 0; nf < 4; ++nf)
                    mma_bf16(acc[mf][nf], ah[mf], bl[nf]);
            #pragma unroll
            for (int mf = 0; mf < 2; ++mf)
                #pragma unroll
                for (int nf = 0; nf < 4; ++nf)
                    mma_bf16(acc[mf][nf], al[mf], bh[nf]);
        }
    };

    // R3 pipeline: LDG(kt+1) in flight during MMA(kt); one sync per chunk.
    ldg_chunk(0);
    cvt_sts(0);
    __syncthreads();
    for (int kt = 0; kt < nch; ++kt) {
        const bool more = (kt + 1 < nch);
        if (more) ldg_chunk(kt + 1);
        mma_chunk(kt & 1);
        if (more) {
            cvt_sts((kt + 1) & 1);
            __syncthreads();
        }
    }
}

// fp32 epilogue (32x32 warp tile)
__device__ __forceinline__ void epi_f32(float (&acc)[2][4][4],
                                        float* __restrict__ Ct, int ldc)
{
    const int lane = threadIdx.x & 31, wid = threadIdx.x >> 5;
    const int wm = wid >> 2, wn = wid & 3;
    #pragma unroll
    for (int mf = 0; mf < 2; ++mf)
        #pragma unroll
        for (int nf = 0; nf < 4; ++nf) {
            int row = wm * 32 + mf * 16 + (lane >> 2);
            int col = wn * 32 + nf * 8 + (lane & 3) * 2;
            *reinterpret_cast<float2*>(Ct + (size_t)row * ldc + col) =
                make_float2(acc[mf][nf][0], acc[mf][nf][1]);
            *reinterpret_cast<float2*>(Ct + (size_t)(row + 8) * ldc + col) =
                make_float2(acc[mf][nf][2], acc[mf][nf][3]);
        }
}

// Stage 1: QKV. grid=(64,8,3), 512 thr.
__global__ __launch_bounds__(NTHR)
void qkv_mma(const float* __restrict__ x,
             const float* __restrict__ Wq,
             const float* __restrict__ Wk,
             const float* __restrict__ Wv)
{
    const int bx = blockIdx.x, by = blockIdx.y, z = blockIdx.z;
    float acc[2][4][4];
    #pragma unroll
    for (int a = 0; a < 2; ++a)
        #pragma unroll
        for (int b = 0; b < 4; ++b)
            #pragma unroll
            for (int c = 0; c < 4; ++c) acc[a][b][c] = 0.0f;

    if (z < 2) {
        const float* W = (z == 0) ? Wq : Wk;
        float* o = (z == 0) ? g_q : g_k;
        mma_core(x + (size_t)bx * 128 * NCH, NCH,
                 W + (size_t)by * 128 * NCH, NCH, NCH / 32, acc);
        epi_f32(acc, o + (size_t)bx * 128 * NCH + by * 128, NCH);
    } else {
        // vt = Wv * x^T : rows c (by), cols t (bx)
        mma_core(Wv + (size_t)by * 128 * NCH, NCH,
                 x + (size_t)bx * 128 * NCH, NCH, NCH / 32, acc);
        epi_f32(acc, g_vt + (size_t)by * 128 * NXT + bx * 128, NXT);
    }
}

// Stage 2: S = Q K^T, lower-triangular tiles. grid=(16,16,NB), 512 thr.
__global__ __launch_bounds__(NTHR)
void qk_mma(int dummy)
{
    if (blockIdx.x > blockIdx.y) return;
    const int b = blockIdx.z;
    float acc[2][4][4];
    #pragma unroll
    for (int a = 0; a < 2; ++a)
        #pragma unroll
        for (int bb = 0; bb < 4; ++bb)
            #pragma unroll
            for (int c = 0; c < 4; ++c) acc[a][bb][c] = 0.0f;
    mma_core(g_q + (size_t)b * NT * NCH + (size_t)blockIdx.y * 128 * NCH, NCH,
             g_k + (size_t)b * NT * NCH + (size_t)blockIdx.x * 128 * NCH, NCH,
             NCH / 32, acc);
    epi_f32(acc, g_s + (size_t)b * NT * NT + (size_t)blockIdx.y * 128 * NT
                     + blockIdx.x * 128, NT);
}

// Stage 3: causal softmax — one warp per row, row in registers, single pass.
// grid=(NT/4, NB), 128 threads (4 warps).
__global__ __launch_bounds__(128)
void softmax_causal(float scale)
{
    const int lane = threadIdx.x & 31;
    const int i = blockIdx.x * 4 + (threadIdx.x >> 5);
    float* row = g_s + ((size_t)blockIdx.y * NT + i) * NT;
    const int len = i + 1;

    float v[64];
    float m = -INFINITY;
    #pragma unroll
    for (int k = 0; k < 64; ++k) {
        const int j = lane + 32 * k;
        v[k] = (j < len) ? row[j] : -INFINITY;
        m = fmaxf(m, v[k]);
    }
    #pragma unroll
    for (int o = 16; o > 0; o >>= 1) m = fmaxf(m, __shfl_xor_sync(0xffffffffu, m, o));

    float s = 0.0f;
    #pragma unroll
    for (int k = 0; k < 64; ++k) {
        float e = __expf((v[k] - m) * scale);   // -inf -> 0
        v[k] = e;
        s += e;
    }
    #pragma unroll
    for (int o = 16; o > 0; o >>= 1) s += __shfl_xor_sync(0xffffffffu, s, o);
    const float inv = 1.0f / s;

    const int jend = ((i >> 7) + 1) << 7;   // zero-pad to 128-row block boundary
    #pragma unroll
    for (int k = 0; k < 64; ++k) {
        const int j = lane + 32 * k;
        if (j < jend) row[j] = v[k] * inv;  // masked entries: v[k]=0 already
    }
}

// Stage 4: out = P vt^T, k-extent clipped. grid=(8,16,NB), 512 thr.
__global__ __launch_bounds__(NTHR)
void pv_mma(float* __restrict__ out)
{
    const int b = blockIdx.z, by = blockIdx.y, bx = blockIdx.x;
    float acc[2][4][4];
    #pragma unroll
    for (int a = 0; a < 2; ++a)
        #pragma unroll
        for (int bb = 0; bb < 4; ++bb)
            #pragma unroll
            for (int c = 0; c < 4; ++c) acc[a][bb][c] = 0.0f;
    mma_core(g_s + (size_t)b * NT * NT + (size_t)by * 128 * NT, NT,
             g_vt + (size_t)bx * 128 * NXT + (size_t)b * NT, NXT,
             (by + 1) * 4, acc);
    epi_f32(acc, out + (size_t)b * NT * NCH + (size_t)by * 128 * NCH + bx * 128, NCH);
}

extern "C" void kernel_launch(void* const* d_in, const int* in_sizes, int n_in,
                              void* d_out, int out_size)
{
    const float* x  = (const float*)d_in[0];
    const float* Wq = (const float*)d_in[1];
    const float* Wk = (const float*)d_in[2];
    const float* Wv = (const float*)d_in[3];
    float* out = (float*)d_out;

    static bool attr_done = false;
    if (!attr_done) {
        cudaFuncSetAttribute(qkv_mma, cudaFuncAttributeMaxDynamicSharedMemorySize, SMEM_TOTAL);
        cudaFuncSetAttribute(qk_mma,  cudaFuncAttributeMaxDynamicSharedMemorySize, SMEM_TOTAL);
        cudaFuncSetAttribute(pv_mma,  cudaFuncAttributeMaxDynamicSharedMemorySize, SMEM_TOTAL);
        attr_done = true;
    }

    dim3 blk512(NTHR), blk128(128);
    qkv_mma<<<dim3(64, 8, 3), blk512, SMEM_TOTAL>>>(x, Wq, Wk, Wv);
    qk_mma<<<dim3(16, 16, NB), blk512, SMEM_TOTAL>>>(0);
    softmax_causal<<<dim3(NT / 4, NB), blk128>>>(1.0f / 32.0f);   // 1024^-0.5
    pv_mma<<<dim3(8, 16, NB), blk512, SMEM_TOTAL>>>(out);
}

// round 8
// speedup vs baseline: 1.1200x; 1.1200x over previous
#include <cuda_runtime.h>
#include <cstdint>
#include <math.h>

// ---------------------------------------------------------------------------
// Attention_3856880632117 — R3 GEMM core (measured best) + fast softmax.
// mma.sync.m16n8k16.bf16 + ldmatrix (plain sm_103: no tcgen05).
// GEMM hot loop: LDG(fp32)->reg, HMMA current chunk, cvt+STS next chunk,
// ONE __syncthreads per K-chunk. 256 thr, 2x4 warps, 64x32 warp tiles.
//
//   Stage 1: q = x Wq^T, k = x Wk^T, vt = Wv x^T
//   Stage 2: S = q k^T (lower-triangular tiles only)
//   Stage 3: causal softmax — warp-per-row, row in registers, single pass
//   Stage 4: out = P vt^T (k-extent clipped)
// C = A*B^T, fp32 I/O; fp32-accurate via C += Ah*Bh + Ah*Bl + Al*Bh.
// ---------------------------------------------------------------------------

#define NB 4
#define NT 2048
#define NCH 1024
#define NXT (NB * NT)

// Scratch (allocation-free rule: __device__ globals).
__device__ float g_q [(size_t)NB * NT * NCH];    // 32 MB
__device__ float g_k [(size_t)NB * NT * NCH];    // 32 MB
__device__ float g_vt[(size_t)NCH * NXT];        // 32 MB, [c][b*T + t]
__device__ float g_s [(size_t)NB * NT * NT];     // 64 MB (scores -> probs)

// ---------------- tensor-core primitives ------------------------------------
__device__ __forceinline__ void ldsm4(uint32_t* r, uint32_t addr) {
    asm volatile("ldmatrix.sync.aligned.m8n8.x4.shared.b16 {%0,%1,%2,%3}, [%4];"
                 : "=r"(r[0]), "=r"(r[1]), "=r"(r[2]), "=r"(r[3]) : "r"(addr));
}
__device__ __forceinline__ void mma_bf16(float* c, const uint32_t* a, const uint32_t* b) {
    asm volatile(
        "mma.sync.aligned.m16n8k16.row.col.f32.bf16.bf16.f32 "
        "{%0,%1,%2,%3},{%4,%5,%6,%7},{%8,%9},{%0,%1,%2,%3};"
        : "+f"(c[0]), "+f"(c[1]), "+f"(c[2]), "+f"(c[3])
        : "r"(a[0]), "r"(a[1]), "r"(a[2]), "r"(a[3]), "r"(b[0]), "r"(b[1]));
}
__device__ __forceinline__ uint32_t smem_u32(const void* p) {
    uint32_t a;
    asm("{ .reg .u64 t; cvta.to.shared.u64 t, %1; cvt.u32.u64 %0, t; }"
        : "=r"(a) : "l"(p));
    return a;
}
__device__ __forceinline__ uint32_t pack_bf16x2(float hi, float lo) {
    uint32_t r;
    asm("cvt.rn.bf16x2.f32 %0, %1, %2;" : "=r"(r) : "f"(hi), "f"(lo));
    return r;
}

// ---------------------------------------------------------------------------
// SMEM geometry: bf16 tiles 128 rows x 32 cols, row pitch 40 elems (80 B).
// Regions per stage: Ahi | Alo | Bhi | Blo, 10240 B each; 2 stages.
// ---------------------------------------------------------------------------
#define PITCHB     80
#define REGION     10240
#define STAGE_B    40960
#define SMEM_TOTAL (2 * STAGE_B)

__device__ __forceinline__ void mma_gemm_tile(
    const float* __restrict__ At, int lda,
    const float* __restrict__ Bt, int ldb,
    float* __restrict__ Ct, int ldc,
    int nch)
{
    extern __shared__ char smraw[];
    char* sm = smraw;
    const uint32_t smu = smem_u32(sm);

    const int tid  = threadIdx.x;
    const int lane = tid & 31;
    const int wid  = tid >> 5;
    const int wm   = wid >> 2;   // 0..1  (64 rows each)
    const int wn   = wid & 3;    // 0..3  (32 cols each)

    const int ldr = tid >> 3;          // 0..31 (+32*i)
    const int ldc4 = tid & 7;          // float4 group within 32-float row

    const uint32_t aRowByte = (uint32_t)(lane & 15) * PITCHB + (uint32_t)(lane >> 4) * 16;
    const uint32_t bRowByte = (uint32_t)(((lane >> 4) << 3) + (lane & 7)) * PITCHB
                            + (uint32_t)((lane >> 3) & 1) * 16;

    float acc[4][4][4];
    #pragma unroll
    for (int mf = 0; mf < 4; ++mf)
        #pragma unroll
        for (int nf = 0; nf < 4; ++nf)
            #pragma unroll
            for (int q = 0; q < 4; ++q) acc[mf][nf][q] = 0.0f;

    float4 pa[4], pb[4];

    auto ldg_chunk = [&](int kt) {
        const int kb = kt * 32;
        #pragma unroll
        for (int i = 0; i < 4; ++i) {
            int r = ldr + i * 32;
            pa[i] = *reinterpret_cast<const float4*>(At + (size_t)r * lda + kb + ldc4 * 4);
            pb[i] = *reinterpret_cast<const float4*>(Bt + (size_t)r * ldb + kb + ldc4 * 4);
        }
    };

    auto cvt_sts = [&](int buf) {
        char* base = sm + buf * STAGE_B;
        #pragma unroll
        for (int i = 0; i < 4; ++i) {
            int r = ldr + i * 32;
            uint32_t off = (uint32_t)r * PITCHB + (uint32_t)ldc4 * 8;
            {   // A
                float4 v = pa[i];
                uint32_t h01 = pack_bf16x2(v.y, v.x);
                uint32_t h23 = pack_bf16x2(v.w, v.z);
                float hx = __uint_as_float(h01 << 16);
                float hy = __uint_as_float(h01 & 0xFFFF0000u);
                float hz = __uint_as_float(h23 << 16);
                float hw = __uint_as_float(h23 & 0xFFFF0000u);
                uint32_t l01 = pack_bf16x2(v.y - hy, v.x - hx);
                uint32_t l23 = pack_bf16x2(v.w - hw, v.z - hz);
                *reinterpret_cast<uint2*>(base + off)          = make_uint2(h01, h23);
                *reinterpret_cast<uint2*>(base + REGION + off) = make_uint2(l01, l23);
            }
            {   // B
                float4 v = pb[i];
                uint32_t h01 = pack_bf16x2(v.y, v.x);
                uint32_t h23 = pack_bf16x2(v.w, v.z);
                float hx = __uint_as_float(h01 << 16);
                float hy = __uint_as_float(h01 & 0xFFFF0000u);
                float hz = __uint_as_float(h23 << 16);
                float hw = __uint_as_float(h23 & 0xFFFF0000u);
                uint32_t l01 = pack_bf16x2(v.y - hy, v.x - hx);
                uint32_t l23 = pack_bf16x2(v.w - hw, v.z - hz);
                *reinterpret_cast<uint2*>(base + 2 * REGION + off) = make_uint2(h01, h23);
                *reinterpret_cast<uint2*>(base + 3 * REGION + off) = make_uint2(l01, l23);
            }
        }
    };

    auto mma_chunk = [&](int buf) {
        const uint32_t sbase = smu + (uint32_t)buf * STAGE_B;
        #pragma unroll
        for (int sk = 0; sk < 2; ++sk) {
            uint32_t ah[4][4], al[4][4], bh[4][2], bl[4][2];
            const uint32_t aBase = sbase + (uint32_t)(wm * 64) * PITCHB + aRowByte
                                 + (uint32_t)sk * 32;
            #pragma unroll
            for (int mf = 0; mf < 4; ++mf) {
                ldsm4(ah[mf], aBase + (uint32_t)mf * (16 * PITCHB));
                ldsm4(al[mf], aBase + (uint32_t)mf * (16 * PITCHB) + REGION);
            }
            const uint32_t bBase = sbase + 2 * REGION + (uint32_t)(wn * 32) * PITCHB
                                 + bRowByte + (uint32_t)sk * 32;
            #pragma unroll
            for (int p = 0; p < 2; ++p) {
                uint32_t t[4];
                ldsm4(t, bBase + (uint32_t)p * (16 * PITCHB));
                bh[2 * p][0] = t[0]; bh[2 * p][1] = t[1];
                bh[2 * p + 1][0] = t[2]; bh[2 * p + 1][1] = t[3];
                ldsm4(t, bBase + (uint32_t)p * (16 * PITCHB) + REGION);
                bl[2 * p][0] = t[0]; bl[2 * p][1] = t[1];
                bl[2 * p + 1][0] = t[2]; bl[2 * p + 1][1] = t[3];
            }
            #pragma unroll
            for (int mf = 0; mf < 4; ++mf)
                #pragma unroll
                for (int nf = 0; nf < 4; ++nf)
                    mma_bf16(acc[mf][nf], ah[mf], bh[nf]);
            #pragma unroll
            for (int mf = 0; mf < 4; ++mf)
                #pragma unroll
                for (int nf = 0; nf < 4; ++nf)
                    mma_bf16(acc[mf][nf], ah[mf], bl[nf]);
            #pragma unroll
            for (int mf = 0; mf < 4; ++mf)
                #pragma unroll
                for (int nf = 0; nf < 4; ++nf)
                    mma_bf16(acc[mf][nf], al[mf], bh[nf]);
        }
    };

    // pipeline: LDG(kt+1) in flight while MMA(kt) runs; one sync per chunk
    ldg_chunk(0);
    cvt_sts(0);
    __syncthreads();
    for (int kt = 0; kt < nch; ++kt) {
        const bool more = (kt + 1 < nch);
        if (more) ldg_chunk(kt + 1);
        mma_chunk(kt & 1);
        if (more) {
            cvt_sts((kt + 1) & 1);
            __syncthreads();
        }
    }

    // epilogue
    #pragma unroll
    for (int mf = 0; mf < 4; ++mf) {
        #pragma unroll
        for (int nf = 0; nf < 4; ++nf) {
            int row = wm * 64 + mf * 16 + (lane >> 2);
            int col = wn * 32 + nf * 8 + (lane & 3) * 2;
            float* p0 = Ct + (size_t)row * ldc + col;
            float* p1 = Ct + (size_t)(row + 8) * ldc + col;
            *reinterpret_cast<float2*>(p0) = make_float2(acc[mf][nf][0], acc[mf][nf][1]);
            *reinterpret_cast<float2*>(p1) = make_float2(acc[mf][nf][2], acc[mf][nf][3]);
        }
    }
}

// Stage 1: QKV. grid = (64, 8, 3), 256 thr.
__global__ __launch_bounds__(256, 1)
void qkv_mma(const float* __restrict__ x,
             const float* __restrict__ Wq,
             const float* __restrict__ Wk,
             const float* __restrict__ Wv)
{
    const int bx = blockIdx.x, by = blockIdx.y, z = blockIdx.z;
    if (z == 0) {
        mma_gemm_tile(x + (size_t)bx * 128 * NCH, NCH,
                      Wq + (size_t)by * 128 * NCH, NCH,
                      g_q + (size_t)bx * 128 * NCH + by * 128, NCH, NCH / 32);
    } else if (z == 1) {
        mma_gemm_tile(x + (size_t)bx * 128 * NCH, NCH,
                      Wk + (size_t)by * 128 * NCH, NCH,
                      g_k + (size_t)bx * 128 * NCH + by * 128, NCH, NCH / 32);
    } else {
        mma_gemm_tile(Wv + (size_t)by * 128 * NCH, NCH,
                      x + (size_t)bx * 128 * NCH, NCH,
                      g_vt + (size_t)by * 128 * NXT + bx * 128, NXT, NCH / 32);
    }
}

// Stage 2: S = Q K^T, lower-triangular tiles. grid = (16, 16, NB)
__global__ __launch_bounds__(256, 1)
void qk_mma(int dummy)
{
    if (blockIdx.x > blockIdx.y) return;
    const int b = blockIdx.z;
    mma_gemm_tile(g_q + (size_t)b * NT * NCH + (size_t)blockIdx.y * 128 * NCH, NCH,
                  g_k + (size_t)b * NT * NCH + (size_t)blockIdx.x * 128 * NCH, NCH,
                  g_s + (size_t)b * NT * NT + (size_t)blockIdx.y * 128 * NT
                      + blockIdx.x * 128, NT, NCH / 32);
}

// Stage 3: causal softmax — one warp per row, row in registers, single pass.
// grid=(NT/4, NB), 128 threads (4 warps).
__global__ __launch_bounds__(128)
void softmax_causal(float scale)
{
    const int lane = threadIdx.x & 31;
    const int i = blockIdx.x * 4 + (threadIdx.x >> 5);
    float* row = g_s + ((size_t)blockIdx.y * NT + i) * NT;
    const int len = i + 1;

    float v[64];
    float m = -INFINITY;
    #pragma unroll
    for (int k = 0; k < 64; ++k) {
        const int j = lane + 32 * k;
        v[k] = (j < len) ? row[j] : -INFINITY;
        m = fmaxf(m, v[k]);
    }
    #pragma unroll
    for (int o = 16; o > 0; o >>= 1) m = fmaxf(m, __shfl_xor_sync(0xffffffffu, m, o));

    float s = 0.0f;
    #pragma unroll
    for (int k = 0; k < 64; ++k) {
        float e = __expf((v[k] - m) * scale);   // -inf -> 0
        v[k] = e;
        s += e;
    }
    #pragma unroll
    for (int o = 16; o > 0; o >>= 1) s += __shfl_xor_sync(0xffffffffu, s, o);
    const float inv = 1.0f / s;

    const int jend = ((i >> 7) + 1) << 7;   // zero-pad to 128-row block boundary
    #pragma unroll
    for (int k = 0; k < 64; ++k) {
        const int j = lane + 32 * k;
        if (j < jend) row[j] = v[k] * inv;  // masked entries already 0
    }
}

// Stage 4: out = P vt^T, k-extent clipped. grid = (8, 16, NB)
__global__ __launch_bounds__(256, 1)
void pv_mma(float* __restrict__ out)
{
    const int b = blockIdx.z, by = blockIdx.y, bx = blockIdx.x;
    mma_gemm_tile(g_s + (size_t)b * NT * NT + (size_t)by * 128 * NT, NT,
                  g_vt + (size_t)bx * 128 * NXT + (size_t)b * NT, NXT,
                  out + (size_t)b * NT * NCH + (size_t)by * 128 * NCH + bx * 128, NCH,
                  (by + 1) * 4);
}

extern "C" void kernel_launch(void* const* d_in, const int* in_sizes, int n_in,
                              void* d_out, int out_size)
{
    const float* x  = (const float*)d_in[0];
    const float* Wq = (const float*)d_in[1];
    const float* Wk = (const float*)d_in[2];
    const float* Wv = (const float*)d_in[3];
    float* out = (float*)d_out;

    static bool attr_done = false;
    if (!attr_done) {
        cudaFuncSetAttribute(qkv_mma, cudaFuncAttributeMaxDynamicSharedMemorySize, SMEM_TOTAL);
        cudaFuncSetAttribute(qk_mma,  cudaFuncAttributeMaxDynamicSharedMemorySize, SMEM_TOTAL);
        cudaFuncSetAttribute(pv_mma,  cudaFuncAttributeMaxDynamicSharedMemorySize, SMEM_TOTAL);
        attr_done = true;
    }

    dim3 blk(256), blk128(128);
    qkv_mma<<<dim3(64, 8, 3), blk, SMEM_TOTAL>>>(x, Wq, Wk, Wv);
    qk_mma<<<dim3(16, 16, NB), blk, SMEM_TOTAL>>>(0);
    softmax_causal<<<dim3(NT / 4, NB), blk128>>>(1.0f / 32.0f);   // 1024^-0.5
    pv_mma<<<dim3(8, 16, NB), blk, SMEM_TOTAL>>>(out);
}

// round 9
// speedup vs baseline: 1.2424x; 1.1093x over previous
#include <cuda_runtime.h>
#include <cstdint>
#include <math.h>

// ---------------------------------------------------------------------------
// Attention_3856880632117 — R8 core + heavy-first pv scheduling + K-chunk 64.
// mma.sync.m16n8k16.bf16 + ldmatrix (plain sm_103: no tcgen05).
// GEMM hot loop: LDG(fp32)->reg, HMMA current chunk, cvt+STS next chunk,
// ONE __syncthreads per K-chunk of 64. 256 thr, 2x4 warps, 64x32 warp tiles.
// C = A*B^T, fp32 I/O; fp32-accurate via C += Ah*Bh + Ah*Bl + Al*Bh.
// ---------------------------------------------------------------------------

#define NB 4
#define NT 2048
#define NCH 1024
#define NXT (NB * NT)

// Scratch (allocation-free rule: __device__ globals).
__device__ float g_q [(size_t)NB * NT * NCH];    // 32 MB
__device__ float g_k [(size_t)NB * NT * NCH];    // 32 MB
__device__ float g_vt[(size_t)NCH * NXT];        // 32 MB, [c][b*T + t]
__device__ float g_s [(size_t)NB * NT * NT];     // 64 MB (scores -> probs)

// ---------------- tensor-core primitives ------------------------------------
__device__ __forceinline__ void ldsm4(uint32_t* r, uint32_t addr) {
    asm volatile("ldmatrix.sync.aligned.m8n8.x4.shared.b16 {%0,%1,%2,%3}, [%4];"
                 : "=r"(r[0]), "=r"(r[1]), "=r"(r[2]), "=r"(r[3]) : "r"(addr));
}
__device__ __forceinline__ void mma_bf16(float* c, const uint32_t* a, const uint32_t* b) {
    asm volatile(
        "mma.sync.aligned.m16n8k16.row.col.f32.bf16.bf16.f32 "
        "{%0,%1,%2,%3},{%4,%5,%6,%7},{%8,%9},{%0,%1,%2,%3};"
        : "+f"(c[0]), "+f"(c[1]), "+f"(c[2]), "+f"(c[3])
        : "r"(a[0]), "r"(a[1]), "r"(a[2]), "r"(a[3]), "r"(b[0]), "r"(b[1]));
}
__device__ __forceinline__ uint32_t smem_u32(const void* p) {
    uint32_t a;
    asm("{ .reg .u64 t; cvta.to.shared.u64 t, %1; cvt.u32.u64 %0, t; }"
        : "=r"(a) : "l"(p));
    return a;
}
__device__ __forceinline__ uint32_t pack_bf16x2(float hi, float lo) {
    uint32_t r;
    asm("cvt.rn.bf16x2.f32 %0, %1, %2;" : "=r"(r) : "f"(hi), "f"(lo));
    return r;
}

// ---------------------------------------------------------------------------
// SMEM geometry (K-chunk 64): bf16 tiles 128 rows x 64 cols = 128B payload,
// 144B pitch (36 words; 36 mod 32 = 4 -> 8-row ldmatrix wavefronts hit all
// 32 banks). Regions per stage: Ahi|Alo|Bhi|Blo, 18432B each; 2 stages.
// ---------------------------------------------------------------------------
#define PITCHB     144
#define REGION     18432
#define STAGE_B    73728
#define SMEM_TOTAL (2 * STAGE_B)   // 147456 B

__device__ __forceinline__ void mma_gemm_tile(
    const float* __restrict__ At, int lda,
    const float* __restrict__ Bt, int ldb,
    float* __restrict__ Ct, int ldc,
    int nch)                               // K-chunks of 64
{
    extern __shared__ char smraw[];
    char* sm = smraw;
    const uint32_t smu = smem_u32(sm);

    const int tid  = threadIdx.x;
    const int lane = tid & 31;
    const int wid  = tid >> 5;
    const int wm   = wid >> 2;   // 0..1  (64 rows each)
    const int wn   = wid & 3;    // 0..3  (32 cols each)

    // gmem load coords: 8 float4 per thread per tensor per chunk
    const int ldr = tid >> 4;          // 0..15 (+16*i)
    const int ldc4 = tid & 15;         // float4 group within 64-float row

    const uint32_t aRowByte = (uint32_t)(lane & 15) * PITCHB + (uint32_t)(lane >> 4) * 16;
    const uint32_t bRowByte = (uint32_t)(((lane >> 4) << 3) + (lane & 7)) * PITCHB
                            + (uint32_t)((lane >> 3) & 1) * 16;

    float acc[4][4][4];
    #pragma unroll
    for (int mf = 0; mf < 4; ++mf)
        #pragma unroll
        for (int nf = 0; nf < 4; ++nf)
            #pragma unroll
            for (int q = 0; q < 4; ++q) acc[mf][nf][q] = 0.0f;

    float4 pa[8], pb[8];

    auto ldg_chunk = [&](int kt) {
        const int kb = kt * 64;
        #pragma unroll
        for (int i = 0; i < 8; ++i) {
            int r = ldr + i * 16;
            pa[i] = *reinterpret_cast<const float4*>(At + (size_t)r * lda + kb + ldc4 * 4);
            pb[i] = *reinterpret_cast<const float4*>(Bt + (size_t)r * ldb + kb + ldc4 * 4);
        }
    };

    auto cvt_sts = [&](int buf) {
        char* base = sm + buf * STAGE_B;
        #pragma unroll
        for (int i = 0; i < 8; ++i) {
            int r = ldr + i * 16;
            uint32_t off = (uint32_t)r * PITCHB + (uint32_t)ldc4 * 8;
            {   // A
                float4 v = pa[i];
                uint32_t h01 = pack_bf16x2(v.y, v.x);
                uint32_t h23 = pack_bf16x2(v.w, v.z);
                float hx = __uint_as_float(h01 << 16);
                float hy = __uint_as_float(h01 & 0xFFFF0000u);
                float hz = __uint_as_float(h23 << 16);
                float hw = __uint_as_float(h23 & 0xFFFF0000u);
                uint32_t l01 = pack_bf16x2(v.y - hy, v.x - hx);
                uint32_t l23 = pack_bf16x2(v.w - hw, v.z - hz);
                *reinterpret_cast<uint2*>(base + off)          = make_uint2(h01, h23);
                *reinterpret_cast<uint2*>(base + REGION + off) = make_uint2(l01, l23);
            }
            {   // B
                float4 v = pb[i];
                uint32_t h01 = pack_bf16x2(v.y, v.x);
                uint32_t h23 = pack_bf16x2(v.w, v.z);
                float hx = __uint_as_float(h01 << 16);
                float hy = __uint_as_float(h01 & 0xFFFF0000u);
                float hz = __uint_as_float(h23 << 16);
                float hw = __uint_as_float(h23 & 0xFFFF0000u);
                uint32_t l01 = pack_bf16x2(v.y - hy, v.x - hx);
                uint32_t l23 = pack_bf16x2(v.w - hw, v.z - hz);
                *reinterpret_cast<uint2*>(base + 2 * REGION + off) = make_uint2(h01, h23);
                *reinterpret_cast<uint2*>(base + 3 * REGION + off) = make_uint2(l01, l23);
            }
        }
    };

    auto mma_chunk = [&](int buf) {
        const uint32_t sbase = smu + (uint32_t)buf * STAGE_B;
        #pragma unroll
        for (int sk = 0; sk < 4; ++sk) {   // 4 sub-chunks of K=16 (32B)
            uint32_t ah[4][4], al[4][4], bh[4][2], bl[4][2];
            const uint32_t aBase = sbase + (uint32_t)(wm * 64) * PITCHB + aRowByte
                                 + (uint32_t)sk * 32;
            #pragma unroll
            for (int mf = 0; mf < 4; ++mf) {
                ldsm4(ah[mf], aBase + (uint32_t)mf * (16 * PITCHB));
                ldsm4(al[mf], aBase + (uint32_t)mf * (16 * PITCHB) + REGION);
            }
            const uint32_t bBase = sbase + 2 * REGION + (uint32_t)(wn * 32) * PITCHB
                                 + bRowByte + (uint32_t)sk * 32;
            #pragma unroll
            for (int p = 0; p < 2; ++p) {
                uint32_t t[4];
                ldsm4(t, bBase + (uint32_t)p * (16 * PITCHB));
                bh[2 * p][0] = t[0]; bh[2 * p][1] = t[1];
                bh[2 * p + 1][0] = t[2]; bh[2 * p + 1][1] = t[3];
                ldsm4(t, bBase + (uint32_t)p * (16 * PITCHB) + REGION);
                bl[2 * p][0] = t[0]; bl[2 * p][1] = t[1];
                bl[2 * p + 1][0] = t[2]; bl[2 * p + 1][1] = t[3];
            }
            #pragma unroll
            for (int mf = 0; mf < 4; ++mf)
                #pragma unroll
                for (int nf = 0; nf < 4; ++nf)
                    mma_bf16(acc[mf][nf], ah[mf], bh[nf]);
            #pragma unroll
            for (int mf = 0; mf < 4; ++mf)
                #pragma unroll
                for (int nf = 0; nf < 4; ++nf)
                    mma_bf16(acc[mf][nf], ah[mf], bl[nf]);
            #pragma unroll
            for (int mf = 0; mf < 4; ++mf)
                #pragma unroll
                for (int nf = 0; nf < 4; ++nf)
                    mma_bf16(acc[mf][nf], al[mf], bh[nf]);
        }
    };

    // pipeline: LDG(kt+1) in flight while MMA(kt) runs; one sync per chunk
    ldg_chunk(0);
    cvt_sts(0);
    __syncthreads();
    for (int kt = 0; kt < nch; ++kt) {
        const bool more = (kt + 1 < nch);
        if (more) ldg_chunk(kt + 1);
        mma_chunk(kt & 1);
        if (more) {
            cvt_sts((kt + 1) & 1);
            __syncthreads();
        }
    }

    // epilogue
    #pragma unroll
    for (int mf = 0; mf < 4; ++mf) {
        #pragma unroll
        for (int nf = 0; nf < 4; ++nf) {
            int row = wm * 64 + mf * 16 + (lane >> 2);
            int col = wn * 32 + nf * 8 + (lane & 3) * 2;
            float* p0 = Ct + (size_t)row * ldc + col;
            float* p1 = Ct + (size_t)(row + 8) * ldc + col;
            *reinterpret_cast<float2*>(p0) = make_float2(acc[mf][nf][0], acc[mf][nf][1]);
            *reinterpret_cast<float2*>(p1) = make_float2(acc[mf][nf][2], acc[mf][nf][3]);
        }
    }
}

// Stage 1: QKV. grid = (64, 8, 3), 256 thr. nch = 1024/64 = 16.
__global__ __launch_bounds__(256, 1)
void qkv_mma(const float* __restrict__ x,
             const float* __restrict__ Wq,
             const float* __restrict__ Wk,
             const float* __restrict__ Wv)
{
    const int bx = blockIdx.x, by = blockIdx.y, z = blockIdx.z;
    if (z == 0) {
        mma_gemm_tile(x + (size_t)bx * 128 * NCH, NCH,
                      Wq + (size_t)by * 128 * NCH, NCH,
                      g_q + (size_t)bx * 128 * NCH + by * 128, NCH, NCH / 64);
    } else if (z == 1) {
        mma_gemm_tile(x + (size_t)bx * 128 * NCH, NCH,
                      Wk + (size_t)by * 128 * NCH, NCH,
                      g_k + (size_t)bx * 128 * NCH + by * 128, NCH, NCH / 64);
    } else {
        mma_gemm_tile(Wv + (size_t)by * 128 * NCH, NCH,
                      x + (size_t)bx * 128 * NCH, NCH,
                      g_vt + (size_t)by * 128 * NXT + bx * 128, NXT, NCH / 64);
    }
}

// Stage 2: S = Q K^T, lower-triangular tiles. grid = (16, 16, NB)
__global__ __launch_bounds__(256, 1)
void qk_mma(int dummy)
{
    if (blockIdx.x > blockIdx.y) return;
    const int b = blockIdx.z;
    mma_gemm_tile(g_q + (size_t)b * NT * NCH + (size_t)blockIdx.y * 128 * NCH, NCH,
                  g_k + (size_t)b * NT * NCH + (size_t)blockIdx.x * 128 * NCH, NCH,
                  g_s + (size_t)b * NT * NT + (size_t)blockIdx.y * 128 * NT
                      + blockIdx.x * 128, NT, NCH / 64);
}

// Stage 3: causal softmax — one warp per row, row in registers, single pass.
// grid=(NT/4, NB), 128 threads (4 warps).
__global__ __launch_bounds__(128)
void softmax_causal(float scale)
{
    const int lane = threadIdx.x & 31;
    const int i = blockIdx.x * 4 + (threadIdx.x >> 5);
    float* row = g_s + ((size_t)blockIdx.y * NT + i) * NT;
    const int len = i + 1;

    float v[64];
    float m = -INFINITY;
    #pragma unroll
    for (int k = 0; k < 64; ++k) {
        const int j = lane + 32 * k;
        v[k] = (j < len) ? row[j] : -INFINITY;
        m = fmaxf(m, v[k]);
    }
    #pragma unroll
    for (int o = 16; o > 0; o >>= 1) m = fmaxf(m, __shfl_xor_sync(0xffffffffu, m, o));

    float s = 0.0f;
    #pragma unroll
    for (int k = 0; k < 64; ++k) {
        float e = __expf((v[k] - m) * scale);   // -inf -> 0
        v[k] = e;
        s += e;
    }
    #pragma unroll
    for (int o = 16; o > 0; o >>= 1) s += __shfl_xor_sync(0xffffffffu, s, o);
    const float inv = 1.0f / s;

    const int jend = ((i >> 7) + 1) << 7;   // zero-pad to 128-row block boundary
    #pragma unroll
    for (int k = 0; k < 64; ++k) {
        const int j = lane + 32 * k;
        if (j < jend) row[j] = v[k] * inv;  // masked entries already 0
    }
}

// Stage 4: out = P vt^T, k-extent clipped, HEAVY-FIRST (by reversed so the
// largest-K CTAs launch in wave 1 and light CTAs fill the tail).
// grid = (8, 16, NB)
__global__ __launch_bounds__(256, 1)
void pv_mma(float* __restrict__ out)
{
    const int b = blockIdx.z, bx = blockIdx.x;
    const int by = 15 - blockIdx.y;              // heavy first
    mma_gemm_tile(g_s + (size_t)b * NT * NT + (size_t)by * 128 * NT, NT,
                  g_vt + (size_t)bx * 128 * NXT + (size_t)b * NT, NXT,
                  out + (size_t)b * NT * NCH + (size_t)by * 128 * NCH + bx * 128, NCH,
                  (by + 1) * 2);                  // K-chunks of 64
}

extern "C" void kernel_launch(void* const* d_in, const int* in_sizes, int n_in,
                              void* d_out, int out_size)
{
    const float* x  = (const float*)d_in[0];
    const float* Wq = (const float*)d_in[1];
    const float* Wk = (const float*)d_in[2];
    const float* Wv = (const float*)d_in[3];
    float* out = (float*)d_out;

    static bool attr_done = false;
    if (!attr_done) {
        cudaFuncSetAttribute(qkv_mma, cudaFuncAttributeMaxDynamicSharedMemorySize, SMEM_TOTAL);
        cudaFuncSetAttribute(qk_mma,  cudaFuncAttributeMaxDynamicSharedMemorySize, SMEM_TOTAL);
        cudaFuncSetAttribute(pv_mma,  cudaFuncAttributeMaxDynamicSharedMemorySize, SMEM_TOTAL);
        attr_done = true;
    }

    dim3 blk(256), blk128(128);
    qkv_mma<<<dim3(64, 8, 3), blk, SMEM_TOTAL>>>(x, Wq, Wk, Wv);
    qk_mma<<<dim3(16, 16, NB), blk, SMEM_TOTAL>>>(0);
    softmax_causal<<<dim3(NT / 4, NB), blk128>>>(1.0f / 32.0f);   // 1024^-0.5
    pv_mma<<<dim3(8, 16, NB), blk, SMEM_TOTAL>>>(out);
}

// round 10
// speedup vs baseline: 1.4366x; 1.1563x over previous
#include <cuda_runtime.h>
#include <cstdint>
#include <math.h>

// ---------------------------------------------------------------------------
// Attention_3856880632117 — R9 core; qkv switched to fp16 2-term split.
// mma.sync m16n8k16 (bf16 & fp16) + ldmatrix (plain sm_103: no tcgen05).
// GEMM hot loop: LDG(fp32)->reg, HMMA current chunk, cvt+STS next chunk,
// ONE __syncthreads per K-chunk of 64. 256 thr, 2x4 warps, 64x32 warp tiles.
//
//   qkv (fp16 2-term):  C += Ah*Bh + Ah*Bl      (residual 2^-11 -> ~5e-4)
//   qk/pv (bf16 3-term): C += Ah*Bh + Ah*Bl + Al*Bh   (~1.6e-5)
// ---------------------------------------------------------------------------

#define NB 4
#define NT 2048
#define NCH 1024
#define NXT (NB * NT)

// Scratch (allocation-free rule: __device__ globals).
__device__ float g_q [(size_t)NB * NT * NCH];    // 32 MB
__device__ float g_k [(size_t)NB * NT * NCH];    // 32 MB
__device__ float g_vt[(size_t)NCH * NXT];        // 32 MB, [c][b*T + t]
__device__ float g_s [(size_t)NB * NT * NT];     // 64 MB (scores -> probs)

// ---------------- tensor-core primitives ------------------------------------
__device__ __forceinline__ void ldsm4(uint32_t* r, uint32_t addr) {
    asm volatile("ldmatrix.sync.aligned.m8n8.x4.shared.b16 {%0,%1,%2,%3}, [%4];"
                 : "=r"(r[0]), "=r"(r[1]), "=r"(r[2]), "=r"(r[3]) : "r"(addr));
}
__device__ __forceinline__ void mma_bf16(float* c, const uint32_t* a, const uint32_t* b) {
    asm volatile(
        "mma.sync.aligned.m16n8k16.row.col.f32.bf16.bf16.f32 "
        "{%0,%1,%2,%3},{%4,%5,%6,%7},{%8,%9},{%0,%1,%2,%3};"
        : "+f"(c[0]), "+f"(c[1]), "+f"(c[2]), "+f"(c[3])
        : "r"(a[0]), "r"(a[1]), "r"(a[2]), "r"(a[3]), "r"(b[0]), "r"(b[1]));
}
__device__ __forceinline__ void mma_f16(float* c, const uint32_t* a, const uint32_t* b) {
    asm volatile(
        "mma.sync.aligned.m16n8k16.row.col.f32.f16.f16.f32 "
        "{%0,%1,%2,%3},{%4,%5,%6,%7},{%8,%9},{%0,%1,%2,%3};"
        : "+f"(c[0]), "+f"(c[1]), "+f"(c[2]), "+f"(c[3])
        : "r"(a[0]), "r"(a[1]), "r"(a[2]), "r"(a[3]), "r"(b[0]), "r"(b[1]));
}
__device__ __forceinline__ uint32_t smem_u32(const void* p) {
    uint32_t a;
    asm("{ .reg .u64 t; cvta.to.shared.u64 t, %1; cvt.u32.u64 %0, t; }"
        : "=r"(a) : "l"(p));
    return a;
}
__device__ __forceinline__ uint32_t pack_bf16x2(float hi, float lo) {
    uint32_t r;
    asm("cvt.rn.bf16x2.f32 %0, %1, %2;" : "=r"(r) : "f"(hi), "f"(lo));
    return r;
}
__device__ __forceinline__ uint32_t pack_f16x2(float hi, float lo) {
    uint32_t r;
    asm("cvt.rn.f16x2.f32 %0, %1, %2;" : "=r"(r) : "f"(hi), "f"(lo));
    return r;
}
__device__ __forceinline__ void unpack_f16x2(uint32_t h, float& lo, float& hi) {
    asm("{ .reg .b16 l, u; mov.b32 {l, u}, %2; cvt.f32.f16 %0, l; cvt.f32.f16 %1, u; }"
        : "=f"(lo), "=f"(hi) : "r"(h));
}

// ---------------------------------------------------------------------------
// SMEM geometry (K-chunk 64): 128 rows x 128B payload, 144B pitch
// (36 words; 36 mod 32 = 4 -> conflict-free ldmatrix wavefronts).
// bf16 core: 4 regions (Ah|Al|Bh|Bl); fp16 2-term core: 3 regions (Ah|Bh|Bl).
// ---------------------------------------------------------------------------
#define PITCHB     144
#define REGION     18432
#define STAGE_B    (4 * REGION)          // 73728
#define SMEM_TOTAL (2 * STAGE_B)         // 147456
#define STAGE_H    (3 * REGION)          // 55296
#define SMEM_H     (2 * STAGE_H)         // 110592

// ======================= bf16 3-term core (qk, pv) ==========================
__device__ __forceinline__ void mma_gemm_tile(
    const float* __restrict__ At, int lda,
    const float* __restrict__ Bt, int ldb,
    float* __restrict__ Ct, int ldc,
    int nch)
{
    extern __shared__ char smraw[];
    char* sm = smraw;
    const uint32_t smu = smem_u32(sm);

    const int tid  = threadIdx.x;
    const int lane = tid & 31;
    const int wid  = tid >> 5;
    const int wm   = wid >> 2;
    const int wn   = wid & 3;

    const int ldr = tid >> 4;          // 0..15 (+16*i)
    const int ldc4 = tid & 15;

    const uint32_t aRowByte = (uint32_t)(lane & 15) * PITCHB + (uint32_t)(lane >> 4) * 16;
    const uint32_t bRowByte = (uint32_t)(((lane >> 4) << 3) + (lane & 7)) * PITCHB
                            + (uint32_t)((lane >> 3) & 1) * 16;

    float acc[4][4][4];
    #pragma unroll
    for (int mf = 0; mf < 4; ++mf)
        #pragma unroll
        for (int nf = 0; nf < 4; ++nf)
            #pragma unroll
            for (int q = 0; q < 4; ++q) acc[mf][nf][q] = 0.0f;

    float4 pa[8], pb[8];

    auto ldg_chunk = [&](int kt) {
        const int kb = kt * 64;
        #pragma unroll
        for (int i = 0; i < 8; ++i) {
            int r = ldr + i * 16;
            pa[i] = *reinterpret_cast<const float4*>(At + (size_t)r * lda + kb + ldc4 * 4);
            pb[i] = *reinterpret_cast<const float4*>(Bt + (size_t)r * ldb + kb + ldc4 * 4);
        }
    };

    auto cvt_sts = [&](int buf) {
        char* base = sm + buf * STAGE_B;
        #pragma unroll
        for (int i = 0; i < 8; ++i) {
            int r = ldr + i * 16;
            uint32_t off = (uint32_t)r * PITCHB + (uint32_t)ldc4 * 8;
            {
                float4 v = pa[i];
                uint32_t h01 = pack_bf16x2(v.y, v.x);
                uint32_t h23 = pack_bf16x2(v.w, v.z);
                float hx = __uint_as_float(h01 << 16);
                float hy = __uint_as_float(h01 & 0xFFFF0000u);
                float hz = __uint_as_float(h23 << 16);
                float hw = __uint_as_float(h23 & 0xFFFF0000u);
                uint32_t l01 = pack_bf16x2(v.y - hy, v.x - hx);
                uint32_t l23 = pack_bf16x2(v.w - hw, v.z - hz);
                *reinterpret_cast<uint2*>(base + off)          = make_uint2(h01, h23);
                *reinterpret_cast<uint2*>(base + REGION + off) = make_uint2(l01, l23);
            }
            {
                float4 v = pb[i];
                uint32_t h01 = pack_bf16x2(v.y, v.x);
                uint32_t h23 = pack_bf16x2(v.w, v.z);
                float hx = __uint_as_float(h01 << 16);
                float hy = __uint_as_float(h01 & 0xFFFF0000u);
                float hz = __uint_as_float(h23 << 16);
                float hw = __uint_as_float(h23 & 0xFFFF0000u);
                uint32_t l01 = pack_bf16x2(v.y - hy, v.x - hx);
                uint32_t l23 = pack_bf16x2(v.w - hw, v.z - hz);
                *reinterpret_cast<uint2*>(base + 2 * REGION + off) = make_uint2(h01, h23);
                *reinterpret_cast<uint2*>(base + 3 * REGION + off) = make_uint2(l01, l23);
            }
        }
    };

    auto mma_chunk = [&](int buf) {
        const uint32_t sbase = smu + (uint32_t)buf * STAGE_B;
        #pragma unroll
        for (int sk = 0; sk < 4; ++sk) {
            uint32_t ah[4][4], al[4][4], bh[4][2], bl[4][2];
            const uint32_t aBase = sbase + (uint32_t)(wm * 64) * PITCHB + aRowByte
                                 + (uint32_t)sk * 32;
            #pragma unroll
            for (int mf = 0; mf < 4; ++mf) {
                ldsm4(ah[mf], aBase + (uint32_t)mf * (16 * PITCHB));
                ldsm4(al[mf], aBase + (uint32_t)mf * (16 * PITCHB) + REGION);
            }
            const uint32_t bBase = sbase + 2 * REGION + (uint32_t)(wn * 32) * PITCHB
                                 + bRowByte + (uint32_t)sk * 32;
            #pragma unroll
            for (int p = 0; p < 2; ++p) {
                uint32_t t[4];
                ldsm4(t, bBase + (uint32_t)p * (16 * PITCHB));
                bh[2 * p][0] = t[0]; bh[2 * p][1] = t[1];
                bh[2 * p + 1][0] = t[2]; bh[2 * p + 1][1] = t[3];
                ldsm4(t, bBase + (uint32_t)p * (16 * PITCHB) + REGION);
                bl[2 * p][0] = t[0]; bl[2 * p][1] = t[1];
                bl[2 * p + 1][0] = t[2]; bl[2 * p + 1][1] = t[3];
            }
            #pragma unroll
            for (int mf = 0; mf < 4; ++mf)
                #pragma unroll
                for (int nf = 0; nf < 4; ++nf)
                    mma_bf16(acc[mf][nf], ah[mf], bh[nf]);
            #pragma unroll
            for (int mf = 0; mf < 4; ++mf)
                #pragma unroll
                for (int nf = 0; nf < 4; ++nf)
                    mma_bf16(acc[mf][nf], ah[mf], bl[nf]);
            #pragma unroll
            for (int mf = 0; mf < 4; ++mf)
                #pragma unroll
                for (int nf = 0; nf < 4; ++nf)
                    mma_bf16(acc[mf][nf], al[mf], bh[nf]);
        }
    };

    ldg_chunk(0);
    cvt_sts(0);
    __syncthreads();
    for (int kt = 0; kt < nch; ++kt) {
        const bool more = (kt + 1 < nch);
        if (more) ldg_chunk(kt + 1);
        mma_chunk(kt & 1);
        if (more) {
            cvt_sts((kt + 1) & 1);
            __syncthreads();
        }
    }

    #pragma unroll
    for (int mf = 0; mf < 4; ++mf) {
        #pragma unroll
        for (int nf = 0; nf < 4; ++nf) {
            int row = wm * 64 + mf * 16 + (lane >> 2);
            int col = wn * 32 + nf * 8 + (lane & 3) * 2;
            float* p0 = Ct + (size_t)row * ldc + col;
            float* p1 = Ct + (size_t)(row + 8) * ldc + col;
            *reinterpret_cast<float2*>(p0) = make_float2(acc[mf][nf][0], acc[mf][nf][1]);
            *reinterpret_cast<float2*>(p1) = make_float2(acc[mf][nf][2], acc[mf][nf][3]);
        }
    }
}

// ======================= fp16 2-term core (qkv) ==============================
// C += Ah*Bh + Ah*Bl. A stored hi-only; B stored hi+lo. 3 SMEM regions.
__device__ __forceinline__ void mma_gemm_tile_f16(
    const float* __restrict__ At, int lda,
    const float* __restrict__ Bt, int ldb,
    float* __restrict__ Ct, int ldc,
    int nch)
{
    extern __shared__ char smraw[];
    char* sm = smraw;
    const uint32_t smu = smem_u32(sm);

    const int tid  = threadIdx.x;
    const int lane = tid & 31;
    const int wid  = tid >> 5;
    const int wm   = wid >> 2;
    const int wn   = wid & 3;

    const int ldr = tid >> 4;
    const int ldc4 = tid & 15;

    const uint32_t aRowByte = (uint32_t)(lane & 15) * PITCHB + (uint32_t)(lane >> 4) * 16;
    const uint32_t bRowByte = (uint32_t)(((lane >> 4) << 3) + (lane & 7)) * PITCHB
                            + (uint32_t)((lane >> 3) & 1) * 16;

    float acc[4][4][4];
    #pragma unroll
    for (int mf = 0; mf < 4; ++mf)
        #pragma unroll
        for (int nf = 0; nf < 4; ++nf)
            #pragma unroll
            for (int q = 0; q < 4; ++q) acc[mf][nf][q] = 0.0f;

    float4 pa[8], pb[8];

    auto ldg_chunk = [&](int kt) {
        const int kb = kt * 64;
        #pragma unroll
        for (int i = 0; i < 8; ++i) {
            int r = ldr + i * 16;
            pa[i] = *reinterpret_cast<const float4*>(At + (size_t)r * lda + kb + ldc4 * 4);
            pb[i] = *reinterpret_cast<const float4*>(Bt + (size_t)r * ldb + kb + ldc4 * 4);
        }
    };

    auto cvt_sts = [&](int buf) {
        char* base = sm + buf * STAGE_H;
        #pragma unroll
        for (int i = 0; i < 8; ++i) {
            int r = ldr + i * 16;
            uint32_t off = (uint32_t)r * PITCHB + (uint32_t)ldc4 * 8;
            {   // A: hi only
                float4 v = pa[i];
                uint32_t h01 = pack_f16x2(v.y, v.x);
                uint32_t h23 = pack_f16x2(v.w, v.z);
                *reinterpret_cast<uint2*>(base + off) = make_uint2(h01, h23);
            }
            {   // B: hi + lo
                float4 v = pb[i];
                uint32_t h01 = pack_f16x2(v.y, v.x);
                uint32_t h23 = pack_f16x2(v.w, v.z);
                float fx, fy, fz, fw;
                unpack_f16x2(h01, fx, fy);
                unpack_f16x2(h23, fz, fw);
                uint32_t l01 = pack_f16x2(v.y - fy, v.x - fx);
                uint32_t l23 = pack_f16x2(v.w - fw, v.z - fz);
                *reinterpret_cast<uint2*>(base + REGION + off)     = make_uint2(h01, h23);
                *reinterpret_cast<uint2*>(base + 2 * REGION + off) = make_uint2(l01, l23);
            }
        }
    };

    auto mma_chunk = [&](int buf) {
        const uint32_t sbase = smu + (uint32_t)buf * STAGE_H;
        #pragma unroll
        for (int sk = 0; sk < 4; ++sk) {
            uint32_t ah[4][4], bh[4][2], bl[4][2];
            const uint32_t aBase = sbase + (uint32_t)(wm * 64) * PITCHB + aRowByte
                                 + (uint32_t)sk * 32;
            #pragma unroll
            for (int mf = 0; mf < 4; ++mf)
                ldsm4(ah[mf], aBase + (uint32_t)mf * (16 * PITCHB));
            const uint32_t bBase = sbase + REGION + (uint32_t)(wn * 32) * PITCHB
                                 + bRowByte + (uint32_t)sk * 32;
            #pragma unroll
            for (int p = 0; p < 2; ++p) {
                uint32_t t[4];
                ldsm4(t, bBase + (uint32_t)p * (16 * PITCHB));
                bh[2 * p][0] = t[0]; bh[2 * p][1] = t[1];
                bh[2 * p + 1][0] = t[2]; bh[2 * p + 1][1] = t[3];
                ldsm4(t, bBase + (uint32_t)p * (16 * PITCHB) + REGION);
                bl[2 * p][0] = t[0]; bl[2 * p][1] = t[1];
                bl[2 * p + 1][0] = t[2]; bl[2 * p + 1][1] = t[3];
            }
            #pragma unroll
            for (int mf = 0; mf < 4; ++mf)
                #pragma unroll
                for (int nf = 0; nf < 4; ++nf)
                    mma_f16(acc[mf][nf], ah[mf], bh[nf]);
            #pragma unroll
            for (int mf = 0; mf < 4; ++mf)
                #pragma unroll
                for (int nf = 0; nf < 4; ++nf)
                    mma_f16(acc[mf][nf], ah[mf], bl[nf]);
        }
    };

    ldg_chunk(0);
    cvt_sts(0);
    __syncthreads();
    for (int kt = 0; kt < nch; ++kt) {
        const bool more = (kt + 1 < nch);
        if (more) ldg_chunk(kt + 1);
        mma_chunk(kt & 1);
        if (more) {
            cvt_sts((kt + 1) & 1);
            __syncthreads();
        }
    }

    #pragma unroll
    for (int mf = 0; mf < 4; ++mf) {
        #pragma unroll
        for (int nf = 0; nf < 4; ++nf) {
            int row = wm * 64 + mf * 16 + (lane >> 2);
            int col = wn * 32 + nf * 8 + (lane & 3) * 2;
            float* p0 = Ct + (size_t)row * ldc + col;
            float* p1 = Ct + (size_t)(row + 8) * ldc + col;
            *reinterpret_cast<float2*>(p0) = make_float2(acc[mf][nf][0], acc[mf][nf][1]);
            *reinterpret_cast<float2*>(p1) = make_float2(acc[mf][nf][2], acc[mf][nf][3]);
        }
    }
}

// Stage 1: QKV (fp16 2-term). grid = (64, 8, 3), 256 thr.
__global__ __launch_bounds__(256, 1)
void qkv_mma(const float* __restrict__ x,
             const float* __restrict__ Wq,
             const float* __restrict__ Wk,
             const float* __restrict__ Wv)
{
    const int bx = blockIdx.x, by = blockIdx.y, z = blockIdx.z;
    if (z == 0) {
        mma_gemm_tile_f16(x + (size_t)bx * 128 * NCH, NCH,
                          Wq + (size_t)by * 128 * NCH, NCH,
                          g_q + (size_t)bx * 128 * NCH + by * 128, NCH, NCH / 64);
    } else if (z == 1) {
        mma_gemm_tile_f16(x + (size_t)bx * 128 * NCH, NCH,
                          Wk + (size_t)by * 128 * NCH, NCH,
                          g_k + (size_t)bx * 128 * NCH + by * 128, NCH, NCH / 64);
    } else {
        mma_gemm_tile_f16(Wv + (size_t)by * 128 * NCH, NCH,
                          x + (size_t)bx * 128 * NCH, NCH,
                          g_vt + (size_t)by * 128 * NXT + bx * 128, NXT, NCH / 64);
    }
}

// Stage 2: S = Q K^T (bf16 3-term), lower-triangular tiles. grid = (16,16,NB)
__global__ __launch_bounds__(256, 1)
void qk_mma(int dummy)
{
    if (blockIdx.x > blockIdx.y) return;
    const int b = blockIdx.z;
    mma_gemm_tile(g_q + (size_t)b * NT * NCH + (size_t)blockIdx.y * 128 * NCH, NCH,
                  g_k + (size_t)b * NT * NCH + (size_t)blockIdx.x * 128 * NCH, NCH,
                  g_s + (size_t)b * NT * NT + (size_t)blockIdx.y * 128 * NT
                      + blockIdx.x * 128, NT, NCH / 64);
}

// Stage 3: causal softmax — one warp per row, single pass.
__global__ __launch_bounds__(128)
void softmax_causal(float scale)
{
    const int lane = threadIdx.x & 31;
    const int i = blockIdx.x * 4 + (threadIdx.x >> 5);
    float* row = g_s + ((size_t)blockIdx.y * NT + i) * NT;
    const int len = i + 1;

    float v[64];
    float m = -INFINITY;
    #pragma unroll
    for (int k = 0; k < 64; ++k) {
        const int j = lane + 32 * k;
        v[k] = (j < len) ? row[j] : -INFINITY;
        m = fmaxf(m, v[k]);
    }
    #pragma unroll
    for (int o = 16; o > 0; o >>= 1) m = fmaxf(m, __shfl_xor_sync(0xffffffffu, m, o));

    float s = 0.0f;
    #pragma unroll
    for (int k = 0; k < 64; ++k) {
        float e = __expf((v[k] - m) * scale);
        v[k] = e;
        s += e;
    }
    #pragma unroll
    for (int o = 16; o > 0; o >>= 1) s += __shfl_xor_sync(0xffffffffu, s, o);
    const float inv = 1.0f / s;

    const int jend = ((i >> 7) + 1) << 7;
    #pragma unroll
    for (int k = 0; k < 64; ++k) {
        const int j = lane + 32 * k;
        if (j < jend) row[j] = v[k] * inv;
    }
}

// Stage 4: out = P vt^T (bf16 3-term), heavy-first. grid = (8, 16, NB)
__global__ __launch_bounds__(256, 1)
void pv_mma(float* __restrict__ out)
{
    const int b = blockIdx.z, bx = blockIdx.x;
    const int by = 15 - blockIdx.y;
    mma_gemm_tile(g_s + (size_t)b * NT * NT + (size_t)by * 128 * NT, NT,
                  g_vt + (size_t)bx * 128 * NXT + (size_t)b * NT, NXT,
                  out + (size_t)b * NT * NCH + (size_t)by * 128 * NCH + bx * 128, NCH,
                  (by + 1) * 2);
}

extern "C" void kernel_launch(void* const* d_in, const int* in_sizes, int n_in,
                              void* d_out, int out_size)
{
    const float* x  = (const float*)d_in[0];
    const float* Wq = (const float*)d_in[1];
    const float* Wk = (const float*)d_in[2];
    const float* Wv = (const float*)d_in[3];
    float* out = (float*)d_out;

    static bool attr_done = false;
    if (!attr_done) {
        cudaFuncSetAttribute(qkv_mma, cudaFuncAttributeMaxDynamicSharedMemorySize, SMEM_H);
        cudaFuncSetAttribute(qk_mma,  cudaFuncAttributeMaxDynamicSharedMemorySize, SMEM_TOTAL);
        cudaFuncSetAttribute(pv_mma,  cudaFuncAttributeMaxDynamicSharedMemorySize, SMEM_TOTAL);
        attr_done = true;
    }

    dim3 blk(256), blk128(128);
    qkv_mma<<<dim3(64, 8, 3), blk, SMEM_H>>>(x, Wq, Wk, Wv);
    qk_mma<<<dim3(16, 16, NB), blk, SMEM_TOTAL>>>(0);
    softmax_causal<<<dim3(NT / 4, NB), blk128>>>(1.0f / 32.0f);   // 1024^-0.5
    pv_mma<<<dim3(8, 16, NB), blk, SMEM_TOTAL>>>(out);
}

// round 11
// speedup vs baseline: 1.6446x; 1.1448x over previous
#include <cuda_runtime.h>
#include <cstdint>
#include <math.h>

// ---------------------------------------------------------------------------
// Attention_3856880632117 — all GEMM stages fp16 2-term split.
// mma.sync.m16n8k16.f16 + ldmatrix (plain sm_103: no tcgen05).
// GEMM hot loop: LDG(fp32)->reg, HMMA current chunk, cvt+STS next chunk,
// ONE __syncthreads per K-chunk of 64. 256 thr, 2x4 warps, 64x32 warp tiles.
//
// 2-term split: C += Ah*Bh + Ah*Bl (A hi-only, B hi+lo; dropped A-residual
// term ~2^-11). Calibrated per-stage normwise error ~3.3e-4; 3-stage total
// ~6.5e-4 < 1e-3 gate.
//   Stage 1: q = x Wq^T, k = x Wk^T, vt = Wv x^T   (vt: [c][b*T+t])
//   Stage 2: S = q k^T (lower-triangular tiles only)
//   Stage 3: causal softmax — warp-per-row, single pass
//   Stage 4: out = P vt^T (k-extent clipped, heavy-first)
// ---------------------------------------------------------------------------

#define NB 4
#define NT 2048
#define NCH 1024
#define NXT (NB * NT)

// Scratch (allocation-free rule: __device__ globals).
__device__ float g_q [(size_t)NB * NT * NCH];    // 32 MB
__device__ float g_k [(size_t)NB * NT * NCH];    // 32 MB
__device__ float g_vt[(size_t)NCH * NXT];        // 32 MB, [c][b*T + t]
__device__ float g_s [(size_t)NB * NT * NT];     // 64 MB (scores -> probs)

// ---------------- tensor-core primitives ------------------------------------
__device__ __forceinline__ void ldsm4(uint32_t* r, uint32_t addr) {
    asm volatile("ldmatrix.sync.aligned.m8n8.x4.shared.b16 {%0,%1,%2,%3}, [%4];"
                 : "=r"(r[0]), "=r"(r[1]), "=r"(r[2]), "=r"(r[3]) : "r"(addr));
}
__device__ __forceinline__ void mma_f16(float* c, const uint32_t* a, const uint32_t* b) {
    asm volatile(
        "mma.sync.aligned.m16n8k16.row.col.f32.f16.f16.f32 "
        "{%0,%1,%2,%3},{%4,%5,%6,%7},{%8,%9},{%0,%1,%2,%3};"
        : "+f"(c[0]), "+f"(c[1]), "+f"(c[2]), "+f"(c[3])
        : "r"(a[0]), "r"(a[1]), "r"(a[2]), "r"(a[3]), "r"(b[0]), "r"(b[1]));
}
__device__ __forceinline__ uint32_t smem_u32(const void* p) {
    uint32_t a;
    asm("{ .reg .u64 t; cvta.to.shared.u64 t, %1; cvt.u32.u64 %0, t; }"
        : "=r"(a) : "l"(p));
    return a;
}
__device__ __forceinline__ uint32_t pack_f16x2(float hi, float lo) {
    uint32_t r;
    asm("cvt.rn.f16x2.f32 %0, %1, %2;" : "=r"(r) : "f"(hi), "f"(lo));
    return r;
}
__device__ __forceinline__ void unpack_f16x2(uint32_t h, float& lo, float& hi) {
    asm("{ .reg .b16 l, u; mov.b32 {l, u}, %2; cvt.f32.f16 %0, l; cvt.f32.f16 %1, u; }"
        : "=f"(lo), "=f"(hi) : "r"(h));
}

// ---------------------------------------------------------------------------
// SMEM geometry (K-chunk 64): 128 rows x 128B payload, 144B pitch
// (36 words; 36 mod 32 = 4 -> conflict-free ldmatrix wavefronts).
// fp16 2-term core: 3 regions (Ah | Bh | Bl), 2 stages.
// ---------------------------------------------------------------------------
#define PITCHB     144
#define REGION     18432
#define STAGE_H    (3 * REGION)          // 55296
#define SMEM_H     (2 * STAGE_H)         // 110592

// ======================= fp16 2-term core ====================================
// C += Ah*Bh + Ah*Bl. A stored hi-only; B stored hi+lo.
__device__ __forceinline__ void mma_gemm_tile_f16(
    const float* __restrict__ At, int lda,
    const float* __restrict__ Bt, int ldb,
    float* __restrict__ Ct, int ldc,
    int nch)
{
    extern __shared__ char smraw[];
    char* sm = smraw;
    const uint32_t smu = smem_u32(sm);

    const int tid  = threadIdx.x;
    const int lane = tid & 31;
    const int wid  = tid >> 5;
    const int wm   = wid >> 2;   // 0..1  (64 rows each)
    const int wn   = wid & 3;    // 0..3  (32 cols each)

    const int ldr = tid >> 4;          // 0..15 (+16*i)
    const int ldc4 = tid & 15;

    const uint32_t aRowByte = (uint32_t)(lane & 15) * PITCHB + (uint32_t)(lane >> 4) * 16;
    const uint32_t bRowByte = (uint32_t)(((lane >> 4) << 3) + (lane & 7)) * PITCHB
                            + (uint32_t)((lane >> 3) & 1) * 16;

    float acc[4][4][4];
    #pragma unroll
    for (int mf = 0; mf < 4; ++mf)
        #pragma unroll
        for (int nf = 0; nf < 4; ++nf)
            #pragma unroll
            for (int q = 0; q < 4; ++q) acc[mf][nf][q] = 0.0f;

    float4 pa[8], pb[8];

    auto ldg_chunk = [&](int kt) {
        const int kb = kt * 64;
        #pragma unroll
        for (int i = 0; i < 8; ++i) {
            int r = ldr + i * 16;
            pa[i] = *reinterpret_cast<const float4*>(At + (size_t)r * lda + kb + ldc4 * 4);
            pb[i] = *reinterpret_cast<const float4*>(Bt + (size_t)r * ldb + kb + ldc4 * 4);
        }
    };

    auto cvt_sts = [&](int buf) {
        char* base = sm + buf * STAGE_H;
        #pragma unroll
        for (int i = 0; i < 8; ++i) {
            int r = ldr + i * 16;
            uint32_t off = (uint32_t)r * PITCHB + (uint32_t)ldc4 * 8;
            {   // A: hi only
                float4 v = pa[i];
                uint32_t h01 = pack_f16x2(v.y, v.x);
                uint32_t h23 = pack_f16x2(v.w, v.z);
                *reinterpret_cast<uint2*>(base + off) = make_uint2(h01, h23);
            }
            {   // B: hi + lo
                float4 v = pb[i];
                uint32_t h01 = pack_f16x2(v.y, v.x);
                uint32_t h23 = pack_f16x2(v.w, v.z);
                float fx, fy, fz, fw;
                unpack_f16x2(h01, fx, fy);
                unpack_f16x2(h23, fz, fw);
                uint32_t l01 = pack_f16x2(v.y - fy, v.x - fx);
                uint32_t l23 = pack_f16x2(v.w - fw, v.z - fz);
                *reinterpret_cast<uint2*>(base + REGION + off)     = make_uint2(h01, h23);
                *reinterpret_cast<uint2*>(base + 2 * REGION + off) = make_uint2(l01, l23);
            }
        }
    };

    auto mma_chunk = [&](int buf) {
        const uint32_t sbase = smu + (uint32_t)buf * STAGE_H;
        #pragma unroll
        for (int sk = 0; sk < 4; ++sk) {   // 4 sub-chunks of K=16 (32B)
            uint32_t ah[4][4], bh[4][2], bl[4][2];
            const uint32_t aBase = sbase + (uint32_t)(wm * 64) * PITCHB + aRowByte
                                 + (uint32_t)sk * 32;
            #pragma unroll
            for (int mf = 0; mf < 4; ++mf)
                ldsm4(ah[mf], aBase + (uint32_t)mf * (16 * PITCHB));
            const uint32_t bBase = sbase + REGION + (uint32_t)(wn * 32) * PITCHB
                                 + bRowByte + (uint32_t)sk * 32;
            #pragma unroll
            for (int p = 0; p < 2; ++p) {
                uint32_t t[4];
                ldsm4(t, bBase + (uint32_t)p * (16 * PITCHB));
                bh[2 * p][0] = t[0]; bh[2 * p][1] = t[1];
                bh[2 * p + 1][0] = t[2]; bh[2 * p + 1][1] = t[3];
                ldsm4(t, bBase + (uint32_t)p * (16 * PITCHB) + REGION);
                bl[2 * p][0] = t[0]; bl[2 * p][1] = t[1];
                bl[2 * p + 1][0] = t[2]; bl[2 * p + 1][1] = t[3];
            }
            #pragma unroll
            for (int mf = 0; mf < 4; ++mf)
                #pragma unroll
                for (int nf = 0; nf < 4; ++nf)
                    mma_f16(acc[mf][nf], ah[mf], bh[nf]);
            #pragma unroll
            for (int mf = 0; mf < 4; ++mf)
                #pragma unroll
                for (int nf = 0; nf < 4; ++nf)
                    mma_f16(acc[mf][nf], ah[mf], bl[nf]);
        }
    };

    // pipeline: LDG(kt+1) in flight while MMA(kt) runs; one sync per chunk
    ldg_chunk(0);
    cvt_sts(0);
    __syncthreads();
    for (int kt = 0; kt < nch; ++kt) {
        const bool more = (kt + 1 < nch);
        if (more) ldg_chunk(kt + 1);
        mma_chunk(kt & 1);
        if (more) {
            cvt_sts((kt + 1) & 1);
            __syncthreads();
        }
    }

    // epilogue
    #pragma unroll
    for (int mf = 0; mf < 4; ++mf) {
        #pragma unroll
        for (int nf = 0; nf < 4; ++nf) {
            int row = wm * 64 + mf * 16 + (lane >> 2);
            int col = wn * 32 + nf * 8 + (lane & 3) * 2;
            float* p0 = Ct + (size_t)row * ldc + col;
            float* p1 = Ct + (size_t)(row + 8) * ldc + col;
            *reinterpret_cast<float2*>(p0) = make_float2(acc[mf][nf][0], acc[mf][nf][1]);
            *reinterpret_cast<float2*>(p1) = make_float2(acc[mf][nf][2], acc[mf][nf][3]);
        }
    }
}

// Stage 1: QKV. grid = (64, 8, 3), 256 thr. nch = 16.
__global__ __launch_bounds__(256, 1)
void qkv_mma(const float* __restrict__ x,
             const float* __restrict__ Wq,
             const float* __restrict__ Wk,
             const float* __restrict__ Wv)
{
    const int bx = blockIdx.x, by = blockIdx.y, z = blockIdx.z;
    if (z == 0) {
        mma_gemm_tile_f16(x + (size_t)bx * 128 * NCH, NCH,
                          Wq + (size_t)by * 128 * NCH, NCH,
                          g_q + (size_t)bx * 128 * NCH + by * 128, NCH, NCH / 64);
    } else if (z == 1) {
        mma_gemm_tile_f16(x + (size_t)bx * 128 * NCH, NCH,
                          Wk + (size_t)by * 128 * NCH, NCH,
                          g_k + (size_t)bx * 128 * NCH + by * 128, NCH, NCH / 64);
    } else {
        mma_gemm_tile_f16(Wv + (size_t)by * 128 * NCH, NCH,
                          x + (size_t)bx * 128 * NCH, NCH,
                          g_vt + (size_t)by * 128 * NXT + bx * 128, NXT, NCH / 64);
    }
}

// Stage 2: S = Q K^T, lower-triangular tiles. grid = (16, 16, NB)
__global__ __launch_bounds__(256, 1)
void qk_mma(int dummy)
{
    if (blockIdx.x > blockIdx.y) return;
    const int b = blockIdx.z;
    mma_gemm_tile_f16(g_q + (size_t)b * NT * NCH + (size_t)blockIdx.y * 128 * NCH, NCH,
                      g_k + (size_t)b * NT * NCH + (size_t)blockIdx.x * 128 * NCH, NCH,
                      g_s + (size_t)b * NT * NT + (size_t)blockIdx.y * 128 * NT
                          + blockIdx.x * 128, NT, NCH / 64);
}

// Stage 3: causal softmax — one warp per row, row in registers, single pass.
// grid=(NT/4, NB), 128 threads (4 warps).
__global__ __launch_bounds__(128)
void softmax_causal(float scale)
{
    const int lane = threadIdx.x & 31;
    const int i = blockIdx.x * 4 + (threadIdx.x >> 5);
    float* row = g_s + ((size_t)blockIdx.y * NT + i) * NT;
    const int len = i + 1;

    float v[64];
    float m = -INFINITY;
    #pragma unroll
    for (int k = 0; k < 64; ++k) {
        const int j = lane + 32 * k;
        v[k] = (j < len) ? row[j] : -INFINITY;
        m = fmaxf(m, v[k]);
    }
    #pragma unroll
    for (int o = 16; o > 0; o >>= 1) m = fmaxf(m, __shfl_xor_sync(0xffffffffu, m, o));

    float s = 0.0f;
    #pragma unroll
    for (int k = 0; k < 64; ++k) {
        float e = __expf((v[k] - m) * scale);   // -inf -> 0
        v[k] = e;
        s += e;
    }
    #pragma unroll
    for (int o = 16; o > 0; o >>= 1) s += __shfl_xor_sync(0xffffffffu, s, o);
    const float inv = 1.0f / s;

    const int jend = ((i >> 7) + 1) << 7;   // zero-pad to 128-row block boundary
    #pragma unroll
    for (int k = 0; k < 64; ++k) {
        const int j = lane + 32 * k;
        if (j < jend) row[j] = v[k] * inv;  // masked entries already 0
    }
}

// Stage 4: out = P vt^T, k-extent clipped, heavy-first. grid = (8, 16, NB)
__global__ __launch_bounds__(256, 1)
void pv_mma(float* __restrict__ out)
{
    const int b = blockIdx.z, bx = blockIdx.x;
    const int by = 15 - blockIdx.y;              // heavy first
    mma_gemm_tile_f16(g_s + (size_t)b * NT * NT + (size_t)by * 128 * NT, NT,
                      g_vt + (size_t)bx * 128 * NXT + (size_t)b * NT, NXT,
                      out + (size_t)b * NT * NCH + (size_t)by * 128 * NCH + bx * 128, NCH,
                      (by + 1) * 2);              // K-chunks of 64
}

extern "C" void kernel_launch(void* const* d_in, const int* in_sizes, int n_in,
                              void* d_out, int out_size)
{
    const float* x  = (const float*)d_in[0];
    const float* Wq = (const float*)d_in[1];
    const float* Wk = (const float*)d_in[2];
    const float* Wv = (const float*)d_in[3];
    float* out = (float*)d_out;

    static bool attr_done = false;
    if (!attr_done) {
        cudaFuncSetAttribute(qkv_mma, cudaFuncAttributeMaxDynamicSharedMemorySize, SMEM_H);
        cudaFuncSetAttribute(qk_mma,  cudaFuncAttributeMaxDynamicSharedMemorySize, SMEM_H);
        cudaFuncSetAttribute(pv_mma,  cudaFuncAttributeMaxDynamicSharedMemorySize, SMEM_H);
        attr_done = true;
    }

    dim3 blk(256), blk128(128);
    qkv_mma<<<dim3(64, 8, 3), blk, SMEM_H>>>(x, Wq, Wk, Wv);
    qk_mma<<<dim3(16, 16, NB), blk, SMEM_H>>>(0);
    softmax_causal<<<dim3(NT / 4, NB), blk128>>>(1.0f / 32.0f);   // 1024^-0.5
    pv_mma<<<dim3(8, 16, NB), blk, SMEM_H>>>(out);
}

// round 12
// speedup vs baseline: 2.2540x; 1.3705x over previous
#include <cuda_runtime.h>
#include <cstdint>
#include <math.h>

// ---------------------------------------------------------------------------
// Attention_3856880632117 — all GEMM stages single-term fp16 (Ah*Bh).
// mma.sync.m16n8k16.f16 + ldmatrix (plain sm_103: no tcgen05).
// GEMM hot loop: LDG(fp32)->reg, HMMA current chunk, cvt+STS next chunk,
// ONE __syncthreads per K-chunk of 64. 256 thr, 2x4 warps, 64x32 warp tiles.
//
// Error budget (HW-calibrated): fp16 truncation of both operands gives
// ~4.6e-4 (qkv) + ~2.6e-4 (qk) + ~2.6e-4 (pv) -> ~5.9e-4 total vs 1e-3 gate.
//   Stage 1: q = x Wq^T, k = x Wk^T, vt = Wv x^T   (vt: [c][b*T+t])
//   Stage 2: S = q k^T (lower-triangular tiles only)
//   Stage 3: causal softmax — warp-per-row, single pass
//   Stage 4: out = P vt^T (k-extent clipped, heavy-first)
// ---------------------------------------------------------------------------

#define NB 4
#define NT 2048
#define NCH 1024
#define NXT (NB * NT)

// Scratch (allocation-free rule: __device__ globals).
__device__ float g_q [(size_t)NB * NT * NCH];    // 32 MB
__device__ float g_k [(size_t)NB * NT * NCH];    // 32 MB
__device__ float g_vt[(size_t)NCH * NXT];        // 32 MB, [c][b*T + t]
__device__ float g_s [(size_t)NB * NT * NT];     // 64 MB (scores -> probs)

// ---------------- tensor-core primitives ------------------------------------
__device__ __forceinline__ void ldsm4(uint32_t* r, uint32_t addr) {
    asm volatile("ldmatrix.sync.aligned.m8n8.x4.shared.b16 {%0,%1,%2,%3}, [%4];"
                 : "=r"(r[0]), "=r"(r[1]), "=r"(r[2]), "=r"(r[3]) : "r"(addr));
}
__device__ __forceinline__ void mma_f16(float* c, const uint32_t* a, const uint32_t* b) {
    asm volatile(
        "mma.sync.aligned.m16n8k16.row.col.f32.f16.f16.f32 "
        "{%0,%1,%2,%3},{%4,%5,%6,%7},{%8,%9},{%0,%1,%2,%3};"
        : "+f"(c[0]), "+f"(c[1]), "+f"(c[2]), "+f"(c[3])
        : "r"(a[0]), "r"(a[1]), "r"(a[2]), "r"(a[3]), "r"(b[0]), "r"(b[1]));
}
__device__ __forceinline__ uint32_t smem_u32(const void* p) {
    uint32_t a;
    asm("{ .reg .u64 t; cvta.to.shared.u64 t, %1; cvt.u32.u64 %0, t; }"
        : "=r"(a) : "l"(p));
    return a;
}
__device__ __forceinline__ uint32_t pack_f16x2(float hi, float lo) {
    uint32_t r;
    asm("cvt.rn.f16x2.f32 %0, %1, %2;" : "=r"(r) : "f"(hi), "f"(lo));
    return r;
}

// ---------------------------------------------------------------------------
// SMEM geometry (K-chunk 64): 128 rows x 128B payload, 144B pitch
// (36 words; 36 mod 32 = 4 -> conflict-free ldmatrix wavefronts).
// single-term core: 2 regions (Ah | Bh), 2 stages.
// ---------------------------------------------------------------------------
#define PITCHB     144
#define REGION     18432
#define STAGE_H    (2 * REGION)          // 36864
#define SMEM_H     (2 * STAGE_H)         // 73728

// ======================= single-term fp16 core ===============================
__device__ __forceinline__ void mma_gemm_tile_f16(
    const float* __restrict__ At, int lda,
    const float* __restrict__ Bt, int ldb,
    float* __restrict__ Ct, int ldc,
    int nch)
{
    extern __shared__ char smraw[];
    char* sm = smraw;
    const uint32_t smu = smem_u32(sm);

    const int tid  = threadIdx.x;
    const int lane = tid & 31;
    const int wid  = tid >> 5;
    const int wm   = wid >> 2;   // 0..1  (64 rows each)
    const int wn   = wid & 3;    // 0..3  (32 cols each)

    const int ldr = tid >> 4;          // 0..15 (+16*i)
    const int ldc4 = tid & 15;

    const uint32_t aRowByte = (uint32_t)(lane & 15) * PITCHB + (uint32_t)(lane >> 4) * 16;
    const uint32_t bRowByte = (uint32_t)(((lane >> 4) << 3) + (lane & 7)) * PITCHB
                            + (uint32_t)((lane >> 3) & 1) * 16;

    float acc[4][4][4];
    #pragma unroll
    for (int mf = 0; mf < 4; ++mf)
        #pragma unroll
        for (int nf = 0; nf < 4; ++nf)
            #pragma unroll
            for (int q = 0; q < 4; ++q) acc[mf][nf][q] = 0.0f;

    float4 pa[8], pb[8];

    auto ldg_chunk = [&](int kt) {
        const int kb = kt * 64;
        #pragma unroll
        for (int i = 0; i < 8; ++i) {
            int r = ldr + i * 16;
            pa[i] = *reinterpret_cast<const float4*>(At + (size_t)r * lda + kb + ldc4 * 4);
            pb[i] = *reinterpret_cast<const float4*>(Bt + (size_t)r * ldb + kb + ldc4 * 4);
        }
    };

    auto cvt_sts = [&](int buf) {
        char* base = sm + buf * STAGE_H;
        #pragma unroll
        for (int i = 0; i < 8; ++i) {
            int r = ldr + i * 16;
            uint32_t off = (uint32_t)r * PITCHB + (uint32_t)ldc4 * 8;
            {   // A hi
                float4 v = pa[i];
                *reinterpret_cast<uint2*>(base + off) =
                    make_uint2(pack_f16x2(v.y, v.x), pack_f16x2(v.w, v.z));
            }
            {   // B hi
                float4 v = pb[i];
                *reinterpret_cast<uint2*>(base + REGION + off) =
                    make_uint2(pack_f16x2(v.y, v.x), pack_f16x2(v.w, v.z));
            }
        }
    };

    auto mma_chunk = [&](int buf) {
        const uint32_t sbase = smu + (uint32_t)buf * STAGE_H;
        #pragma unroll
        for (int sk = 0; sk < 4; ++sk) {   // 4 sub-chunks of K=16 (32B)
            uint32_t ah[4][4], bh[4][2];
            const uint32_t aBase = sbase + (uint32_t)(wm * 64) * PITCHB + aRowByte
                                 + (uint32_t)sk * 32;
            #pragma unroll
            for (int mf = 0; mf < 4; ++mf)
                ldsm4(ah[mf], aBase + (uint32_t)mf * (16 * PITCHB));
            const uint32_t bBase = sbase + REGION + (uint32_t)(wn * 32) * PITCHB
                                 + bRowByte + (uint32_t)sk * 32;
            #pragma unroll
            for (int p = 0; p < 2; ++p) {
                uint32_t t[4];
                ldsm4(t, bBase + (uint32_t)p * (16 * PITCHB));
                bh[2 * p][0] = t[0]; bh[2 * p][1] = t[1];
                bh[2 * p + 1][0] = t[2]; bh[2 * p + 1][1] = t[3];
            }
            #pragma unroll
            for (int mf = 0; mf < 4; ++mf)
                #pragma unroll
                for (int nf = 0; nf < 4; ++nf)
                    mma_f16(acc[mf][nf], ah[mf], bh[nf]);
        }
    };

    // pipeline: LDG(kt+1) in flight while MMA(kt) runs; one sync per chunk
    ldg_chunk(0);
    cvt_sts(0);
    __syncthreads();
    for (int kt = 0; kt < nch; ++kt) {
        const bool more = (kt + 1 < nch);
        if (more) ldg_chunk(kt + 1);
        mma_chunk(kt & 1);
        if (more) {
            cvt_sts((kt + 1) & 1);
            __syncthreads();
        }
    }

    // epilogue
    #pragma unroll
    for (int mf = 0; mf < 4; ++mf) {
        #pragma unroll
        for (int nf = 0; nf < 4; ++nf) {
            int row = wm * 64 + mf * 16 + (lane >> 2);
            int col = wn * 32 + nf * 8 + (lane & 3) * 2;
            float* p0 = Ct + (size_t)row * ldc + col;
            float* p1 = Ct + (size_t)(row + 8) * ldc + col;
            *reinterpret_cast<float2*>(p0) = make_float2(acc[mf][nf][0], acc[mf][nf][1]);
            *reinterpret_cast<float2*>(p1) = make_float2(acc[mf][nf][2], acc[mf][nf][3]);
        }
    }
}

// Stage 1: QKV. grid = (64, 8, 3), 256 thr. nch = 16.
__global__ __launch_bounds__(256, 1)
void qkv_mma(const float* __restrict__ x,
             const float* __restrict__ Wq,
             const float* __restrict__ Wk,
             const float* __restrict__ Wv)
{
    const int bx = blockIdx.x, by = blockIdx.y, z = blockIdx.z;
    if (z == 0) {
        mma_gemm_tile_f16(x + (size_t)bx * 128 * NCH, NCH,
                          Wq + (size_t)by * 128 * NCH, NCH,
                          g_q + (size_t)bx * 128 * NCH + by * 128, NCH, NCH / 64);
    } else if (z == 1) {
        mma_gemm_tile_f16(x + (size_t)bx * 128 * NCH, NCH,
                          Wk + (size_t)by * 128 * NCH, NCH,
                          g_k + (size_t)bx * 128 * NCH + by * 128, NCH, NCH / 64);
    } else {
        mma_gemm_tile_f16(Wv + (size_t)by * 128 * NCH, NCH,
                          x + (size_t)bx * 128 * NCH, NCH,
                          g_vt + (size_t)by * 128 * NXT + bx * 128, NXT, NCH / 64);
    }
}

// Stage 2: S = Q K^T, lower-triangular tiles. grid = (16, 16, NB)
__global__ __launch_bounds__(256, 1)
void qk_mma(int dummy)
{
    if (blockIdx.x > blockIdx.y) return;
    const int b = blockIdx.z;
    mma_gemm_tile_f16(g_q + (size_t)b * NT * NCH + (size_t)blockIdx.y * 128 * NCH, NCH,
                      g_k + (size_t)b * NT * NCH + (size_t)blockIdx.x * 128 * NCH, NCH,
                      g_s + (size_t)b * NT * NT + (size_t)blockIdx.y * 128 * NT
                          + blockIdx.x * 128, NT, NCH / 64);
}

// Stage 3: causal softmax — one warp per row, row in registers, single pass.
// grid=(NT/4, NB), 128 threads (4 warps).
__global__ __launch_bounds__(128)
void softmax_causal(float scale)
{
    const int lane = threadIdx.x & 31;
    const int i = blockIdx.x * 4 + (threadIdx.x >> 5);
    float* row = g_s + ((size_t)blockIdx.y * NT + i) * NT;
    const int len = i + 1;

    float v[64];
    float m = -INFINITY;
    #pragma unroll
    for (int k = 0; k < 64; ++k) {
        const int j = lane + 32 * k;
        v[k] = (j < len) ? row[j] : -INFINITY;
        m = fmaxf(m, v[k]);
    }
    #pragma unroll
    for (int o = 16; o > 0; o >>= 1) m = fmaxf(m, __shfl_xor_sync(0xffffffffu, m, o));

    float s = 0.0f;
    #pragma unroll
    for (int k = 0; k < 64; ++k) {
        float e = __expf((v[k] - m) * scale);   // -inf -> 0
        v[k] = e;
        s += e;
    }
    #pragma unroll
    for (int o = 16; o > 0; o >>= 1) s += __shfl_xor_sync(0xffffffffu, s, o);
    const float inv = 1.0f / s;

    const int jend = ((i >> 7) + 1) << 7;   // zero-pad to 128-row block boundary
    #pragma unroll
    for (int k = 0; k < 64; ++k) {
        const int j = lane + 32 * k;
        if (j < jend) row[j] = v[k] * inv;  // masked entries already 0
    }
}

// Stage 4: out = P vt^T, k-extent clipped, heavy-first. grid = (8, 16, NB)
__global__ __launch_bounds__(256, 1)
void pv_mma(float* __restrict__ out)
{
    const int b = blockIdx.z, bx = blockIdx.x;
    const int by = 15 - blockIdx.y;              // heavy first
    mma_gemm_tile_f16(g_s + (size_t)b * NT * NT + (size_t)by * 128 * NT, NT,
                      g_vt + (size_t)bx * 128 * NXT + (size_t)b * NT, NXT,
                      out + (size_t)b * NT * NCH + (size_t)by * 128 * NCH + bx * 128, NCH,
                      (by + 1) * 2);              // K-chunks of 64
}

extern "C" void kernel_launch(void* const* d_in, const int* in_sizes, int n_in,
                              void* d_out, int out_size)
{
    const float* x  = (const float*)d_in[0];
    const float* Wq = (const float*)d_in[1];
    const float* Wk = (const float*)d_in[2];
    const float* Wv = (const float*)d_in[3];
    float* out = (float*)d_out;

    static bool attr_done = false;
    if (!attr_done) {
        cudaFuncSetAttribute(qkv_mma, cudaFuncAttributeMaxDynamicSharedMemorySize, SMEM_H);
        cudaFuncSetAttribute(qk_mma,  cudaFuncAttributeMaxDynamicSharedMemorySize, SMEM_H);
        cudaFuncSetAttribute(pv_mma,  cudaFuncAttributeMaxDynamicSharedMemorySize, SMEM_H);
        attr_done = true;
    }

    dim3 blk(256), blk128(128);
    qkv_mma<<<dim3(64, 8, 3), blk, SMEM_H>>>(x, Wq, Wk, Wv);
    qk_mma<<<dim3(16, 16, NB), blk, SMEM_H>>>(0);
    softmax_causal<<<dim3(NT / 4, NB), blk128>>>(1.0f / 32.0f);   // 1024^-0.5
    pv_mma<<<dim3(8, 16, NB), blk, SMEM_H>>>(out);
}

// round 13
// speedup vs baseline: 2.8030x; 1.2436x over previous
#include <cuda_runtime.h>
#include <cuda_fp16.h>
#include <cstdint>
#include <math.h>

// ---------------------------------------------------------------------------
// Attention_3856880632117 — fp16-resident single-term HMMA pipeline.
// mma.sync.m16n8k16.f16 + ldmatrix + cp.async (plain sm_103: no tcgen05).
// All operands stored fp16 in gmem (bit-identical to R12's in-loop cvt).
// GEMM hot loop: cp.async(fp16) -> ldmatrix -> HMMA, 3-stage ring,
// ONE __syncthreads per K-chunk of 64. 256 thr, 2x4 warps, 64x32 warp tiles,
// 2 CTAs/SM (launch_bounds(256,2); lean loop ~105 regs, no spills).
//
//   Stage 0: cvt x, Wq, Wk, Wv -> fp16
//   Stage 1: q = x Wq^T, k = x Wk^T, vt = Wv x^T   (fp16 outputs)
//   Stage 2: S = q k^T (lower-triangular tiles), fp32 scores
//   Stage 3: causal softmax — warp-per-row, single pass, fp16 P out
//   Stage 4: out = P vt^T (k-extent clipped, heavy-first), fp32 out
// ---------------------------------------------------------------------------

#define NB 4
#define NT 2048
#define NCH 1024
#define NXT (NB * NT)

typedef unsigned short u16;

// Scratch (allocation-free rule: __device__ globals).
__device__ u16  g_x16[(size_t)NXT * NCH];        // 16 MB
__device__ u16  g_w16[3][(size_t)NCH * NCH];     //  6 MB
__device__ u16  g_q16[(size_t)NXT * NCH];        // 16 MB
__device__ u16  g_k16[(size_t)NXT * NCH];        // 16 MB
__device__ u16  g_vt16[(size_t)NCH * NXT];       // 16 MB, [c][b*T + t]
__device__ float g_s [(size_t)NB * NT * NT];     // 64 MB scores
__device__ u16  g_p16[(size_t)NB * NT * NT];     // 32 MB probs

// ---------------- primitives ------------------------------------------------
__device__ __forceinline__ void ldsm4(uint32_t* r, uint32_t addr) {
    asm volatile("ldmatrix.sync.aligned.m8n8.x4.shared.b16 {%0,%1,%2,%3}, [%4];"
                 : "=r"(r[0]), "=r"(r[1]), "=r"(r[2]), "=r"(r[3]) : "r"(addr));
}
__device__ __forceinline__ void mma_f16(float* c, const uint32_t* a, const uint32_t* b) {
    asm volatile(
        "mma.sync.aligned.m16n8k16.row.col.f32.f16.f16.f32 "
        "{%0,%1,%2,%3},{%4,%5,%6,%7},{%8,%9},{%0,%1,%2,%3};"
        : "+f"(c[0]), "+f"(c[1]), "+f"(c[2]), "+f"(c[3])
        : "r"(a[0]), "r"(a[1]), "r"(a[2]), "r"(a[3]), "r"(b[0]), "r"(b[1]));
}
__device__ __forceinline__ uint32_t smem_u32(const void* p) {
    uint32_t a;
    asm("{ .reg .u64 t; cvta.to.shared.u64 t, %1; cvt.u32.u64 %0, t; }"
        : "=r"(a) : "l"(p));
    return a;
}
__device__ __forceinline__ uint32_t pack_f16x2(float hi, float lo) {
    uint32_t r;
    asm("cvt.rn.f16x2.f32 %0, %1, %2;" : "=r"(r) : "f"(hi), "f"(lo));
    return r;
}
__device__ __forceinline__ void cp16(uint32_t dst, const void* src) {
    asm volatile("cp.async.cg.shared.global [%0], [%1], 16;" :: "r"(dst), "l"(src));
}
#define CP_COMMIT() asm volatile("cp.async.commit_group;" ::: "memory")
#define CP_WAIT(n)  asm volatile("cp.async.wait_group %0;" :: "n"(n) : "memory")

// ---------------------------------------------------------------------------
// SMEM (K-chunk 64): fp16 tiles 128 rows x 64 halves = 128B payload, 144B
// pitch (conflict-free ldmatrix). 2 regions (A | B) per stage, 3 stages.
// ---------------------------------------------------------------------------
#define PITCHB     144
#define REGION     18432
#define STAGE_H    (2 * REGION)          // 36864
#define NSTAGE     3
#define SMEM_H     (NSTAGE * STAGE_H)    // 110592

// ======================= fp16 single-term core ===============================
// C = A*B^T over nch K-chunks of 64. EPI16: write fp16; else fp32.
template <bool EPI16>
__device__ __forceinline__ void mma_core(
    const u16* __restrict__ At, int lda,
    const u16* __restrict__ Bt, int ldb,
    void* __restrict__ Ct, int ldc,
    int nch)
{
    extern __shared__ char smraw[];
    const uint32_t smu = smem_u32(smraw);

    const int tid  = threadIdx.x;
    const int lane = tid & 31;
    const int wid  = tid >> 5;
    const int wm   = wid >> 2;   // 0..1  (64 rows each)
    const int wn   = wid & 3;    // 0..3  (32 cols each)

    const int row0 = tid >> 3;   // 0..31 (+32*i), 4 iters -> 128 rows
    const int seg  = tid & 7;    // 16B segment within 128B row payload

    const uint32_t aRowByte = (uint32_t)(lane & 15) * PITCHB + (uint32_t)(lane >> 4) * 16;
    const uint32_t bRowByte = (uint32_t)(((lane >> 4) << 3) + (lane & 7)) * PITCHB
                            + (uint32_t)((lane >> 3) & 1) * 16;

    float acc[4][4][4];
    #pragma unroll
    for (int mf = 0; mf < 4; ++mf)
        #pragma unroll
        for (int nf = 0; nf < 4; ++nf)
            #pragma unroll
            for (int q = 0; q < 4; ++q) acc[mf][nf][q] = 0.0f;

    auto load_chunk = [&](int kt, int buf) {
        const int kb = kt * 64;
        const uint32_t sb = smu + (uint32_t)buf * STAGE_H;
        #pragma unroll
        for (int i = 0; i < 4; ++i) {
            const int r = row0 + i * 32;
            const uint32_t d = sb + (uint32_t)r * PITCHB + (uint32_t)seg * 16;
            cp16(d,          At + (size_t)r * lda + kb + seg * 8);
            cp16(d + REGION, Bt + (size_t)r * ldb + kb + seg * 8);
        }
        CP_COMMIT();
    };

    auto mma_chunk = [&](int buf) {
        const uint32_t sbase = smu + (uint32_t)buf * STAGE_H;
        #pragma unroll
        for (int sk = 0; sk < 4; ++sk) {   // 4 sub-chunks of K=16 (32B)
            uint32_t ah[4][4], bh[4][2];
            const uint32_t aBase = sbase + (uint32_t)(wm * 64) * PITCHB + aRowByte
                                 + (uint32_t)sk * 32;
            #pragma unroll
            for (int mf = 0; mf < 4; ++mf)
                ldsm4(ah[mf], aBase + (uint32_t)mf * (16 * PITCHB));
            const uint32_t bBase = sbase + REGION + (uint32_t)(wn * 32) * PITCHB
                                 + bRowByte + (uint32_t)sk * 32;
            #pragma unroll
            for (int p = 0; p < 2; ++p) {
                uint32_t t[4];
                ldsm4(t, bBase + (uint32_t)p * (16 * PITCHB));
                bh[2 * p][0] = t[0]; bh[2 * p][1] = t[1];
                bh[2 * p + 1][0] = t[2]; bh[2 * p + 1][1] = t[3];
            }
            #pragma unroll
            for (int mf = 0; mf < 4; ++mf)
                #pragma unroll
                for (int nf = 0; nf < 4; ++nf)
                    mma_f16(acc[mf][nf], ah[mf], bh[nf]);
        }
    };

    // 3-stage ring, one barrier per chunk, prefetch distance 2.
    load_chunk(0, 0);
    if (nch > 1) load_chunk(1, 1);
    for (int kt = 0; kt < nch; ++kt) {
        if (kt + 1 < nch) { CP_WAIT(1); } else { CP_WAIT(0); }
        __syncthreads();                 // chunk kt visible; all warps past mma(kt-1)
        mma_chunk(kt % NSTAGE);
        if (kt + 2 < nch)                // buf (kt+2)%3 consumed at iter kt-1
            load_chunk(kt + 2, (kt + 2) % NSTAGE);
    }

    // epilogue
    #pragma unroll
    for (int mf = 0; mf < 4; ++mf) {
        #pragma unroll
        for (int nf = 0; nf < 4; ++nf) {
            const int row = wm * 64 + mf * 16 + (lane >> 2);
            const int col = wn * 32 + nf * 8 + (lane & 3) * 2;
            if (EPI16) {
                u16* C = (u16*)Ct;
                *reinterpret_cast<uint32_t*>(C + (size_t)row * ldc + col) =
                    pack_f16x2(acc[mf][nf][1], acc[mf][nf][0]);
                *reinterpret_cast<uint32_t*>(C + (size_t)(row + 8) * ldc + col) =
                    pack_f16x2(acc[mf][nf][3], acc[mf][nf][2]);
            } else {
                float* C = (float*)Ct;
                *reinterpret_cast<float2*>(C + (size_t)row * ldc + col) =
                    make_float2(acc[mf][nf][0], acc[mf][nf][1]);
                *reinterpret_cast<float2*>(C + (size_t)(row + 8) * ldc + col) =
                    make_float2(acc[mf][nf][2], acc[mf][nf][3]);
            }
        }
    }
}

// Stage 0: fp32 -> fp16 convert, float4 granularity, grid-stride.
__global__ __launch_bounds__(256)
void cvt_f16(const float* __restrict__ src, u16* __restrict__ dst, int n4)
{
    for (int i = blockIdx.x * 256 + threadIdx.x; i < n4; i += gridDim.x * 256) {
        float4 v = reinterpret_cast<const float4*>(src)[i];
        reinterpret_cast<uint2*>(dst)[i] =
            make_uint2(pack_f16x2(v.y, v.x), pack_f16x2(v.w, v.z));
    }
}

// Stage 1: QKV. grid = (64, 8, 3), 256 thr, 2 CTAs/SM. nch = 16.
__global__ __launch_bounds__(256, 2)
void qkv_mma(int dummy)
{
    const int bx = blockIdx.x, by = blockIdx.y, z = blockIdx.z;
    if (z == 0) {
        mma_core<true>(g_x16 + (size_t)bx * 128 * NCH, NCH,
                       g_w16[0] + (size_t)by * 128 * NCH, NCH,
                       g_q16 + (size_t)bx * 128 * NCH + by * 128, NCH, NCH / 64);
    } else if (z == 1) {
        mma_core<true>(g_x16 + (size_t)bx * 128 * NCH, NCH,
                       g_w16[1] + (size_t)by * 128 * NCH, NCH,
                       g_k16 + (size_t)bx * 128 * NCH + by * 128, NCH, NCH / 64);
    } else {
        mma_core<true>(g_w16[2] + (size_t)by * 128 * NCH, NCH,
                       g_x16 + (size_t)bx * 128 * NCH, NCH,
                       g_vt16 + (size_t)by * 128 * NXT + bx * 128, NXT, NCH / 64);
    }
}

// Stage 2: S = Q K^T, lower-triangular tiles. grid = (16, 16, NB)
__global__ __launch_bounds__(256, 2)
void qk_mma(int dummy)
{
    if (blockIdx.x > blockIdx.y) return;
    const int b = blockIdx.z;
    mma_core<false>(g_q16 + (size_t)b * NT * NCH + (size_t)blockIdx.y * 128 * NCH, NCH,
                    g_k16 + (size_t)b * NT * NCH + (size_t)blockIdx.x * 128 * NCH, NCH,
                    g_s + (size_t)b * NT * NT + (size_t)blockIdx.y * 128 * NT
                        + blockIdx.x * 128, NT, NCH / 64);
}

// Stage 3: causal softmax — warp-per-row, single pass; emits fp16 P.
// grid=(NT/4, NB), 128 threads (4 warps).
__global__ __launch_bounds__(128)
void softmax_causal(float scale)
{
    const int lane = threadIdx.x & 31;
    const int i = blockIdx.x * 4 + (threadIdx.x >> 5);
    const size_t ro = ((size_t)blockIdx.y * NT + i) * NT;
    const float* row = g_s + ro;
    const int len = i + 1;

    float v[64];
    float m = -INFINITY;
    #pragma unroll
    for (int k = 0; k < 64; ++k) {
        const int j = lane + 32 * k;
        v[k] = (j < len) ? row[j] : -INFINITY;
        m = fmaxf(m, v[k]);
    }
    #pragma unroll
    for (int o = 16; o > 0; o >>= 1) m = fmaxf(m, __shfl_xor_sync(0xffffffffu, m, o));

    float s = 0.0f;
    #pragma unroll
    for (int k = 0; k < 64; ++k) {
        float e = __expf((v[k] - m) * scale);   // -inf -> 0
        v[k] = e;
        s += e;
    }
    #pragma unroll
    for (int o = 16; o > 0; o >>= 1) s += __shfl_xor_sync(0xffffffffu, s, o);
    const float inv = 1.0f / s;

    const int jend = ((i >> 7) + 1) << 7;   // zero-pad to 128-row block boundary
    #pragma unroll
    for (int k = 0; k < 64; ++k) {
        const int j = lane + 32 * k;
        if (j < jend) {
            __half h = __float2half_rn(v[k] * inv);   // masked entries already 0
            g_p16[ro + j] = *reinterpret_cast<u16*>(&h);
        }
    }
}

// Stage 4: out = P vt^T, k-extent clipped, heavy-first. grid = (8, 16, NB)
__global__ __launch_bounds__(256, 2)
void pv_mma(float* __restrict__ out)
{
    const int b = blockIdx.z, bx = blockIdx.x;
    const int by = 15 - blockIdx.y;              // heavy first
    mma_core<false>(g_p16 + (size_t)b * NT * NT + (size_t)by * 128 * NT, NT,
                    g_vt16 + (size_t)bx * 128 * NXT + (size_t)b * NT, NXT,
                    out + (size_t)b * NT * NCH + (size_t)by * 128 * NCH + bx * 128, NCH,
                    (by + 1) * 2);               // K-chunks of 64
}

extern "C" void kernel_launch(void* const* d_in, const int* in_sizes, int n_in,
                              void* d_out, int out_size)
{
    const float* x  = (const float*)d_in[0];
    const float* Wq = (const float*)d_in[1];
    const float* Wk = (const float*)d_in[2];
    const float* Wv = (const float*)d_in[3];
    float* out = (float*)d_out;

    static bool attr_done = false;
    if (!attr_done) {
        cudaFuncSetAttribute(qkv_mma, cudaFuncAttributeMaxDynamicSharedMemorySize, SMEM_H);
        cudaFuncSetAttribute(qk_mma,  cudaFuncAttributeMaxDynamicSharedMemorySize, SMEM_H);
        cudaFuncSetAttribute(pv_mma,  cudaFuncAttributeMaxDynamicSharedMemorySize, SMEM_H);
        attr_done = true;
    }

    u16 *x16, *w16;
    cudaGetSymbolAddress((void**)&x16, g_x16);
    cudaGetSymbolAddress((void**)&w16, g_w16);

    dim3 blk(256), blk128(128);
    cvt_f16<<<1024, blk>>>(x,  x16, (NXT * NCH) / 4);
    cvt_f16<<<256,  blk>>>(Wq, w16,                      (NCH * NCH) / 4);
    cvt_f16<<<256,  blk>>>(Wk, w16 + (size_t)NCH * NCH,  (NCH * NCH) / 4);
    cvt_f16<<<256,  blk>>>(Wv, w16 + (size_t)2*NCH*NCH,  (NCH * NCH) / 4);

    qkv_mma<<<dim3(64, 8, 3), blk, SMEM_H>>>(0);
    qk_mma<<<dim3(16, 16, NB), blk, SMEM_H>>>(0);
    softmax_causal<<<dim3(NT / 4, NB), blk128>>>(1.0f / 32.0f);   // 1024^-0.5
    pv_mma<<<dim3(8, 16, NB), blk, SMEM_H>>>(out);
}

// round 14
// speedup vs baseline: 2.9414x; 1.0494x over previous
#include <cuda_runtime.h>
#include <cuda_fp16.h>
#include <cstdint>
#include <math.h>

// ---------------------------------------------------------------------------
// Attention_3856880632117 — fp16-resident single-term HMMA pipeline, v2.
// mma.sync.m16n8k16.f16 + ldmatrix + cp.async (plain sm_103: no tcgen05).
// GEMM hot loop: cp.async -> ldmatrix -> HMMA, 3-stage ring, one sync/chunk,
// 256 thr, 2x4 warps, 64x32 warp tiles, 2 CTAs/SM.
//
//   Stage 0: cvt x, Wq, Wk, Wv -> fp16 (single merged launch)
//   Stage 1: q = x Wq^T, k = x Wk^T          (grid (64,8,2))
//   Stage 2: MERGED: S = q k^T (544 triangular tiles) + vt = Wv x^T (512)
//   Stage 3: causal softmax — warp-per-row, paired float2/uint32 I/O
//   Stage 4: out = P vt^T (k-extent clipped, heavy-first)
// ---------------------------------------------------------------------------

#define NB 4
#define NT 2048
#define NCH 1024
#define NXT (NB * NT)

typedef unsigned short u16;

// Scratch (allocation-free rule: __device__ globals).
__device__ u16  g_x16[(size_t)NXT * NCH];
__device__ u16  g_w16[3][(size_t)NCH * NCH];
__device__ u16  g_q16[(size_t)NXT * NCH];
__device__ u16  g_k16[(size_t)NXT * NCH];
__device__ u16  g_vt16[(size_t)NCH * NXT];       // [c][b*T + t]
__device__ float g_s [(size_t)NB * NT * NT];     // fp32 scores
__device__ u16  g_p16[(size_t)NB * NT * NT];     // fp16 probs

// ---------------- primitives ------------------------------------------------
__device__ __forceinline__ void ldsm4(uint32_t* r, uint32_t addr) {
    asm volatile("ldmatrix.sync.aligned.m8n8.x4.shared.b16 {%0,%1,%2,%3}, [%4];"
                 : "=r"(r[0]), "=r"(r[1]), "=r"(r[2]), "=r"(r[3]) : "r"(addr));
}
__device__ __forceinline__ void mma_f16(float* c, const uint32_t* a, const uint32_t* b) {
    asm volatile(
        "mma.sync.aligned.m16n8k16.row.col.f32.f16.f16.f32 "
        "{%0,%1,%2,%3},{%4,%5,%6,%7},{%8,%9},{%0,%1,%2,%3};"
        : "+f"(c[0]), "+f"(c[1]), "+f"(c[2]), "+f"(c[3])
        : "r"(a[0]), "r"(a[1]), "r"(a[2]), "r"(a[3]), "r"(b[0]), "r"(b[1]));
}
__device__ __forceinline__ uint32_t smem_u32(const void* p) {
    uint32_t a;
    asm("{ .reg .u64 t; cvta.to.shared.u64 t, %1; cvt.u32.u64 %0, t; }"
        : "=r"(a) : "l"(p));
    return a;
}
__device__ __forceinline__ uint32_t pack_f16x2(float hi, float lo) {
    uint32_t r;
    asm("cvt.rn.f16x2.f32 %0, %1, %2;" : "=r"(r) : "f"(hi), "f"(lo));
    return r;
}
__device__ __forceinline__ void cp16(uint32_t dst, const void* src) {
    asm volatile("cp.async.cg.shared.global [%0], [%1], 16;" :: "r"(dst), "l"(src));
}
#define CP_COMMIT() asm volatile("cp.async.commit_group;" ::: "memory")
#define CP_WAIT(n)  asm volatile("cp.async.wait_group %0;" :: "n"(n) : "memory")

// ---------------------------------------------------------------------------
// SMEM (K-chunk 64): fp16 tiles 128 rows x 128B payload, 144B pitch
// (conflict-free ldmatrix). 2 regions (A | B) per stage, 3 stages.
// ---------------------------------------------------------------------------
#define PITCHB     144
#define REGION     18432
#define STAGE_H    (2 * REGION)          // 36864
#define NSTAGE     3
#define SMEM_H     (NSTAGE * STAGE_H)    // 110592

// ======================= fp16 single-term core ===============================
template <bool EPI16>
__device__ __forceinline__ void mma_core(
    const u16* __restrict__ At, int lda,
    const u16* __restrict__ Bt, int ldb,
    void* __restrict__ Ct, int ldc,
    int nch)
{
    extern __shared__ char smraw[];
    const uint32_t smu = smem_u32(smraw);

    const int tid  = threadIdx.x;
    const int lane = tid & 31;
    const int wid  = tid >> 5;
    const int wm   = wid >> 2;
    const int wn   = wid & 3;

    const int row0 = tid >> 3;   // 0..31 (+32*i)
    const int seg  = tid & 7;    // 16B segment within 128B payload

    const uint32_t aRowByte = (uint32_t)(lane & 15) * PITCHB + (uint32_t)(lane >> 4) * 16;
    const uint32_t bRowByte = (uint32_t)(((lane >> 4) << 3) + (lane & 7)) * PITCHB
                            + (uint32_t)((lane >> 3) & 1) * 16;

    float acc[4][4][4];
    #pragma unroll
    for (int mf = 0; mf < 4; ++mf)
        #pragma unroll
        for (int nf = 0; nf < 4; ++nf)
            #pragma unroll
            for (int q = 0; q < 4; ++q) acc[mf][nf][q] = 0.0f;

    auto load_chunk = [&](int kt, int buf) {
        const int kb = kt * 64;
        const uint32_t sb = smu + (uint32_t)buf * STAGE_H;
        #pragma unroll
        for (int i = 0; i < 4; ++i) {
            const int r = row0 + i * 32;
            const uint32_t d = sb + (uint32_t)r * PITCHB + (uint32_t)seg * 16;
            cp16(d,          At + (size_t)r * lda + kb + seg * 8);
            cp16(d + REGION, Bt + (size_t)r * ldb + kb + seg * 8);
        }
        CP_COMMIT();
    };

    auto mma_chunk = [&](int buf) {
        const uint32_t sbase = smu + (uint32_t)buf * STAGE_H;
        #pragma unroll
        for (int sk = 0; sk < 4; ++sk) {
            uint32_t ah[4][4], bh[4][2];
            const uint32_t aBase = sbase + (uint32_t)(wm * 64) * PITCHB + aRowByte
                                 + (uint32_t)sk * 32;
            #pragma unroll
            for (int mf = 0; mf < 4; ++mf)
                ldsm4(ah[mf], aBase + (uint32_t)mf * (16 * PITCHB));
            const uint32_t bBase = sbase + REGION + (uint32_t)(wn * 32) * PITCHB
                                 + bRowByte + (uint32_t)sk * 32;
            #pragma unroll
            for (int p = 0; p < 2; ++p) {
                uint32_t t[4];
                ldsm4(t, bBase + (uint32_t)p * (16 * PITCHB));
                bh[2 * p][0] = t[0]; bh[2 * p][1] = t[1];
                bh[2 * p + 1][0] = t[2]; bh[2 * p + 1][1] = t[3];
            }
            #pragma unroll
            for (int mf = 0; mf < 4; ++mf)
                #pragma unroll
                for (int nf = 0; nf < 4; ++nf)
                    mma_f16(acc[mf][nf], ah[mf], bh[nf]);
        }
    };

    load_chunk(0, 0);
    if (nch > 1) load_chunk(1, 1);
    for (int kt = 0; kt < nch; ++kt) {
        if (kt + 1 < nch) { CP_WAIT(1); } else { CP_WAIT(0); }
        __syncthreads();
        mma_chunk(kt % NSTAGE);
        if (kt + 2 < nch)
            load_chunk(kt + 2, (kt + 2) % NSTAGE);
    }

    #pragma unroll
    for (int mf = 0; mf < 4; ++mf) {
        #pragma unroll
        for (int nf = 0; nf < 4; ++nf) {
            const int row = wm * 64 + mf * 16 + (lane >> 2);
            const int col = wn * 32 + nf * 8 + (lane & 3) * 2;
            if (EPI16) {
                u16* C = (u16*)Ct;
                *reinterpret_cast<uint32_t*>(C + (size_t)row * ldc + col) =
                    pack_f16x2(acc[mf][nf][1], acc[mf][nf][0]);
                *reinterpret_cast<uint32_t*>(C + (size_t)(row + 8) * ldc + col) =
                    pack_f16x2(acc[mf][nf][3], acc[mf][nf][2]);
            } else {
                float* C = (float*)Ct;
                *reinterpret_cast<float2*>(C + (size_t)row * ldc + col) =
                    make_float2(acc[mf][nf][0], acc[mf][nf][1]);
                *reinterpret_cast<float2*>(C + (size_t)(row + 8) * ldc + col) =
                    make_float2(acc[mf][nf][2], acc[mf][nf][3]);
            }
        }
    }
}

// Stage 0: merged fp32 -> fp16 convert for x, Wq, Wk, Wv.
#define N4X ((NXT * NCH) / 4)
#define N4W ((NCH * NCH) / 4)
__global__ __launch_bounds__(256)
void cvt_all(const float* __restrict__ x,  const float* __restrict__ Wq,
             const float* __restrict__ Wk, const float* __restrict__ Wv)
{
    const int total = N4X + 3 * N4W;
    for (int i = blockIdx.x * 256 + threadIdx.x; i < total; i += gridDim.x * 256) {
        const float* src; u16* dst; int j;
        if (i < N4X)              { src = x;  dst = g_x16;    j = i; }
        else if (i < N4X + N4W)   { src = Wq; dst = g_w16[0]; j = i - N4X; }
        else if (i < N4X + 2*N4W) { src = Wk; dst = g_w16[1]; j = i - N4X - N4W; }
        else                      { src = Wv; dst = g_w16[2]; j = i - N4X - 2*N4W; }
        float4 v = reinterpret_cast<const float4*>(src)[j];
        reinterpret_cast<uint2*>(dst)[j] =
            make_uint2(pack_f16x2(v.y, v.x), pack_f16x2(v.w, v.z));
    }
}

// Stage 1: q, k projections. grid = (64, 8, 2).
__global__ __launch_bounds__(256, 2)
void qk_proj(int dummy)
{
    const int bx = blockIdx.x, by = blockIdx.y, z = blockIdx.z;
    u16* o = (z == 0) ? g_q16 : g_k16;
    mma_core<true>(g_x16 + (size_t)bx * 128 * NCH, NCH,
                   g_w16[z] + (size_t)by * 128 * NCH, NCH,
                   o + (size_t)bx * 128 * NCH + by * 128, NCH, NCH / 64);
}

// Stage 2 MERGED: S = q k^T (544 triangular tiles) + vt = Wv x^T (512 tiles).
// grid.x = 1056; all CTAs have nch = 16 (equal work).
__global__ __launch_bounds__(256, 2)
void qk_vt(int dummy)
{
    const int idx = blockIdx.x;
    if (idx < 544) {
        const int b = idx / 136;
        const int t = idx - b * 136;
        int by = (int)((sqrtf(8.0f * (float)t + 1.0f) - 1.0f) * 0.5f);
        while ((by + 1) * (by + 2) / 2 <= t) ++by;     // guard fp rounding
        while (by * (by + 1) / 2 > t) --by;
        const int bx = t - by * (by + 1) / 2;          // bx <= by
        mma_core<false>(g_q16 + (size_t)b * NT * NCH + (size_t)by * 128 * NCH, NCH,
                        g_k16 + (size_t)b * NT * NCH + (size_t)bx * 128 * NCH, NCH,
                        g_s + (size_t)b * NT * NT + (size_t)by * 128 * NT
                            + bx * 128, NT, NCH / 64);
    } else {
        const int v = idx - 544;           // 0..511
        const int bx = v & 63;             // t-tile (of 8192)
        const int by = v >> 6;             // c-tile (of 1024)
        mma_core<true>(g_w16[2] + (size_t)by * 128 * NCH, NCH,
                       g_x16 + (size_t)bx * 128 * NCH, NCH,
                       g_vt16 + (size_t)by * 128 * NXT + bx * 128, NXT, NCH / 64);
    }
}

// Stage 3: causal softmax — warp-per-row, float2 loads / uint32 packed stores.
// grid=(NT/4, NB), 128 threads (4 warps).
__global__ __launch_bounds__(128)
void softmax_causal(float scale)
{
    const int lane = threadIdx.x & 31;
    const int i = blockIdx.x * 4 + (threadIdx.x >> 5);
    const size_t ro = ((size_t)blockIdx.y * NT + i) * NT;
    const float* row = g_s + ro;
    const int len = i + 1;

    float2 v[32];
    float m = -INFINITY;
    #pragma unroll
    for (int k = 0; k < 32; ++k) {
        const int j = 2 * (lane + 32 * k);
        float2 p = *reinterpret_cast<const float2*>(row + j);
        p.x = (j     < len) ? p.x : -INFINITY;
        p.y = (j + 1 < len) ? p.y : -INFINITY;
        v[k] = p;
        m = fmaxf(m, fmaxf(p.x, p.y));
    }
    #pragma unroll
    for (int o = 16; o > 0; o >>= 1) m = fmaxf(m, __shfl_xor_sync(0xffffffffu, m, o));

    float s = 0.0f;
    #pragma unroll
    for (int k = 0; k < 32; ++k) {
        float e0 = __expf((v[k].x - m) * scale);   // -inf -> 0
        float e1 = __expf((v[k].y - m) * scale);
        v[k].x = e0; v[k].y = e1;
        s += e0 + e1;
    }
    #pragma unroll
    for (int o = 16; o > 0; o >>= 1) s += __shfl_xor_sync(0xffffffffu, s, o);
    const float inv = 1.0f / s;

    const int jend = ((i >> 7) + 1) << 7;   // zero-pad to 128-row block boundary
    #pragma unroll
    for (int k = 0; k < 32; ++k) {
        const int j = 2 * (lane + 32 * k);
        if (j < jend)
            *reinterpret_cast<uint32_t*>(g_p16 + ro + j) =
                pack_f16x2(v[k].y * inv, v[k].x * inv);
    }
}

// Stage 4: out = P vt^T, k-extent clipped, heavy-first. grid = (8, 16, NB)
__global__ __launch_bounds__(256, 2)
void pv_mma(float* __restrict__ out)
{
    const int b = blockIdx.z, bx = blockIdx.x;
    const int by = 15 - blockIdx.y;              // heavy first
    mma_core<false>(g_p16 + (size_t)b * NT * NT + (size_t)by * 128 * NT, NT,
                    g_vt16 + (size_t)bx * 128 * NXT + (size_t)b * NT, NXT,
                    out + (size_t)b * NT * NCH + (size_t)by * 128 * NCH + bx * 128, NCH,
                    (by + 1) * 2);
}

extern "C" void kernel_launch(void* const* d_in, const int* in_sizes, int n_in,
                              void* d_out, int out_size)
{
    const float* x  = (const float*)d_in[0];
    const float* Wq = (const float*)d_in[1];
    const float* Wk = (const float*)d_in[2];
    const float* Wv = (const float*)d_in[3];
    float* out = (float*)d_out;

    static bool attr_done = false;
    if (!attr_done) {
        cudaFuncSetAttribute(qk_proj, cudaFuncAttributeMaxDynamicSharedMemorySize, SMEM_H);
        cudaFuncSetAttribute(qk_vt,   cudaFuncAttributeMaxDynamicSharedMemorySize, SMEM_H);
        cudaFuncSetAttribute(pv_mma,  cudaFuncAttributeMaxDynamicSharedMemorySize, SMEM_H);
        attr_done = true;
    }

    dim3 blk(256), blk128(128);
    cvt_all<<<2048, blk>>>(x, Wq, Wk, Wv);
    qk_proj<<<dim3(64, 8, 2), blk, SMEM_H>>>(0);
    qk_vt<<<1056, blk, SMEM_H>>>(0);
    softmax_causal<<<dim3(NT / 4, NB), blk128>>>(1.0f / 32.0f);   // 1024^-0.5
    pv_mma<<<dim3(8, 16, NB), blk, SMEM_H>>>(out);
}

// round 15
// speedup vs baseline: 3.3496x; 1.1388x over previous
#include <cuda_runtime.h>
#include <cuda_fp16.h>
#include <cstdint>
#include <math.h>

// ---------------------------------------------------------------------------
// Attention_3856880632117 — fp16-resident single-term HMMA pipeline, v3.
// mma.sync.m16n8k16.f16 + ldmatrix + cp.async (plain sm_103: no tcgen05).
// GEMM hot loop: cp.async -> ldmatrix -> HMMA, 3-stage ring, one sync/chunk,
// 256 thr, 2x4 warps, 64x32 warp tiles, 2 CTAs/SM. nch templated (full
// unroll for the fixed-K stages).
//
//   Stage 0: cvt x, Wq, Wk, Wv -> fp16 (merged, 2x float4 ILP)
//   Stage 1: q = x Wq^T, k = x Wk^T
//   Stage 2: MERGED: S = q k^T (544 triangular tiles) + vt = Wv x^T (512)
//   Stage 3: causal softmax — warp-per-row, paired I/O
//   Stage 4: out = P vt^T (k-extent clipped, globally heavy-first)
// ---------------------------------------------------------------------------

#define NB 4
#define NT 2048
#define NCH 1024
#define NXT (NB * NT)

typedef unsigned short u16;

// Scratch (allocation-free rule: __device__ globals).
__device__ u16  g_x16[(size_t)NXT * NCH];
__device__ u16  g_w16[3][(size_t)NCH * NCH];
__device__ u16  g_q16[(size_t)NXT * NCH];
__device__ u16  g_k16[(size_t)NXT * NCH];
__device__ u16  g_vt16[(size_t)NCH * NXT];       // [c][b*T + t]
__device__ float g_s [(size_t)NB * NT * NT];     // fp32 scores
__device__ u16  g_p16[(size_t)NB * NT * NT];     // fp16 probs

// ---------------- primitives ------------------------------------------------
__device__ __forceinline__ void ldsm4(uint32_t* r, uint32_t addr) {
    asm volatile("ldmatrix.sync.aligned.m8n8.x4.shared.b16 {%0,%1,%2,%3}, [%4];"
                 : "=r"(r[0]), "=r"(r[1]), "=r"(r[2]), "=r"(r[3]) : "r"(addr));
}
__device__ __forceinline__ void mma_f16(float* c, const uint32_t* a, const uint32_t* b) {
    asm volatile(
        "mma.sync.aligned.m16n8k16.row.col.f32.f16.f16.f32 "
        "{%0,%1,%2,%3},{%4,%5,%6,%7},{%8,%9},{%0,%1,%2,%3};"
        : "+f"(c[0]), "+f"(c[1]), "+f"(c[2]), "+f"(c[3])
        : "r"(a[0]), "r"(a[1]), "r"(a[2]), "r"(a[3]), "r"(b[0]), "r"(b[1]));
}
__device__ __forceinline__ uint32_t smem_u32(const void* p) {
    uint32_t a;
    asm("{ .reg .u64 t; cvta.to.shared.u64 t, %1; cvt.u32.u64 %0, t; }"
        : "=r"(a) : "l"(p));
    return a;
}
__device__ __forceinline__ uint32_t pack_f16x2(float hi, float lo) {
    uint32_t r;
    asm("cvt.rn.f16x2.f32 %0, %1, %2;" : "=r"(r) : "f"(hi), "f"(lo));
    return r;
}
__device__ __forceinline__ void cp16(uint32_t dst, const void* src) {
    asm volatile("cp.async.cg.shared.global [%0], [%1], 16;" :: "r"(dst), "l"(src));
}
#define CP_COMMIT() asm volatile("cp.async.commit_group;" ::: "memory")
#define CP_WAIT(n)  asm volatile("cp.async.wait_group %0;" :: "n"(n) : "memory")

// ---------------------------------------------------------------------------
// SMEM (K-chunk 64): fp16 tiles 128 rows x 128B payload, 144B pitch
// (conflict-free ldmatrix). 2 regions (A | B) per stage, 3 stages.
// ---------------------------------------------------------------------------
#define PITCHB     144
#define REGION     18432
#define STAGE_H    (2 * REGION)          // 36864
#define NSTAGE     3
#define SMEM_H     (NSTAGE * STAGE_H)    // 110592

// ======================= fp16 single-term core ===============================
// NCHT > 0: compile-time chunk count (fully unrolled); NCHT == 0: dynamic.
template <bool EPI16, int NCHT>
__device__ __forceinline__ void mma_core(
    const u16* __restrict__ At, int lda,
    const u16* __restrict__ Bt, int ldb,
    void* __restrict__ Ct, int ldc,
    int nch_dyn)
{
    extern __shared__ char smraw[];
    const uint32_t smu = smem_u32(smraw);
    const int nch = (NCHT > 0) ? NCHT : nch_dyn;

    const int tid  = threadIdx.x;
    const int lane = tid & 31;
    const int wid  = tid >> 5;
    const int wm   = wid >> 2;
    const int wn   = wid & 3;

    const int row0 = tid >> 3;   // 0..31 (+32*i)
    const int seg  = tid & 7;    // 16B segment within 128B payload

    const uint32_t aRowByte = (uint32_t)(lane & 15) * PITCHB + (uint32_t)(lane >> 4) * 16;
    const uint32_t bRowByte = (uint32_t)(((lane >> 4) << 3) + (lane & 7)) * PITCHB
                            + (uint32_t)((lane >> 3) & 1) * 16;

    float acc[4][4][4];
    #pragma unroll
    for (int mf = 0; mf < 4; ++mf)
        #pragma unroll
        for (int nf = 0; nf < 4; ++nf)
            #pragma unroll
            for (int q = 0; q < 4; ++q) acc[mf][nf][q] = 0.0f;

    auto load_chunk = [&](int kt, int buf) {
        const int kb = kt * 64;
        const uint32_t sb = smu + (uint32_t)buf * STAGE_H;
        #pragma unroll
        for (int i = 0; i < 4; ++i) {
            const int r = row0 + i * 32;
            const uint32_t d = sb + (uint32_t)r * PITCHB + (uint32_t)seg * 16;
            cp16(d,          At + (size_t)r * lda + kb + seg * 8);
            cp16(d + REGION, Bt + (size_t)r * ldb + kb + seg * 8);
        }
        CP_COMMIT();
    };

    auto mma_chunk = [&](int buf) {
        const uint32_t sbase = smu + (uint32_t)buf * STAGE_H;
        #pragma unroll
        for (int sk = 0; sk < 4; ++sk) {
            uint32_t ah[4][4], bh[4][2];
            const uint32_t aBase = sbase + (uint32_t)(wm * 64) * PITCHB + aRowByte
                                 + (uint32_t)sk * 32;
            #pragma unroll
            for (int mf = 0; mf < 4; ++mf)
                ldsm4(ah[mf], aBase + (uint32_t)mf * (16 * PITCHB));
            const uint32_t bBase = sbase + REGION + (uint32_t)(wn * 32) * PITCHB
                                 + bRowByte + (uint32_t)sk * 32;
            #pragma unroll
            for (int p = 0; p < 2; ++p) {
                uint32_t t[4];
                ldsm4(t, bBase + (uint32_t)p * (16 * PITCHB));
                bh[2 * p][0] = t[0]; bh[2 * p][1] = t[1];
                bh[2 * p + 1][0] = t[2]; bh[2 * p + 1][1] = t[3];
            }
            #pragma unroll
            for (int mf = 0; mf < 4; ++mf)
                #pragma unroll
                for (int nf = 0; nf < 4; ++nf)
                    mma_f16(acc[mf][nf], ah[mf], bh[nf]);
        }
    };

    // 3-stage ring, one barrier per chunk, prefetch distance 2.
    load_chunk(0, 0);
    if (nch > 1) load_chunk(1, 1);
    if (NCHT > 0) {
        #pragma unroll
        for (int kt = 0; kt < NCHT; ++kt) {
            if (kt + 1 < NCHT) { CP_WAIT(1); } else { CP_WAIT(0); }
            __syncthreads();
            mma_chunk(kt % NSTAGE);
            if (kt + 2 < NCHT)
                load_chunk(kt + 2, (kt + 2) % NSTAGE);
        }
    } else {
        for (int kt = 0; kt < nch; ++kt) {
            if (kt + 1 < nch) { CP_WAIT(1); } else { CP_WAIT(0); }
            __syncthreads();
            mma_chunk(kt % NSTAGE);
            if (kt + 2 < nch)
                load_chunk(kt + 2, (kt + 2) % NSTAGE);
        }
    }

    #pragma unroll
    for (int mf = 0; mf < 4; ++mf) {
        #pragma unroll
        for (int nf = 0; nf < 4; ++nf) {
            const int row = wm * 64 + mf * 16 + (lane >> 2);
            const int col = wn * 32 + nf * 8 + (lane & 3) * 2;
            if (EPI16) {
                u16* C = (u16*)Ct;
                *reinterpret_cast<uint32_t*>(C + (size_t)row * ldc + col) =
                    pack_f16x2(acc[mf][nf][1], acc[mf][nf][0]);
                *reinterpret_cast<uint32_t*>(C + (size_t)(row + 8) * ldc + col) =
                    pack_f16x2(acc[mf][nf][3], acc[mf][nf][2]);
            } else {
                float* C = (float*)Ct;
                *reinterpret_cast<float2*>(C + (size_t)row * ldc + col) =
                    make_float2(acc[mf][nf][0], acc[mf][nf][1]);
                *reinterpret_cast<float2*>(C + (size_t)(row + 8) * ldc + col) =
                    make_float2(acc[mf][nf][2], acc[mf][nf][3]);
            }
        }
    }
}

// Stage 0: merged fp32 -> fp16 convert, 2x float4 per thread per iteration.
#define N4X ((NXT * NCH) / 4)
#define N4W ((NCH * NCH) / 4)
__global__ __launch_bounds__(256)
void cvt_all(const float* __restrict__ x,  const float* __restrict__ Wq,
             const float* __restrict__ Wk, const float* __restrict__ Wv)
{
    const int total = N4X + 3 * N4W;
    for (int i0 = (blockIdx.x * 256 + threadIdx.x) * 2; i0 < total;
         i0 += gridDim.x * 512) {
        #pragma unroll
        for (int u = 0; u < 2; ++u) {
            const int i = i0 + u;
            if (i >= total) break;
            const float* src; u16* dst; int j;
            if (i < N4X)              { src = x;  dst = g_x16;    j = i; }
            else if (i < N4X + N4W)   { src = Wq; dst = g_w16[0]; j = i - N4X; }
            else if (i < N4X + 2*N4W) { src = Wk; dst = g_w16[1]; j = i - N4X - N4W; }
            else                      { src = Wv; dst = g_w16[2]; j = i - N4X - 2*N4W; }
            float4 v = reinterpret_cast<const float4*>(src)[j];
            reinterpret_cast<uint2*>(dst)[j] =
                make_uint2(pack_f16x2(v.y, v.x), pack_f16x2(v.w, v.z));
        }
    }
}

// Stage 1: q, k projections. grid = (64, 8, 2). Fully unrolled nch=16.
__global__ __launch_bounds__(256, 2)
void qk_proj(int dummy)
{
    const int bx = blockIdx.x, by = blockIdx.y, z = blockIdx.z;
    u16* o = (z == 0) ? g_q16 : g_k16;
    mma_core<true, 16>(g_x16 + (size_t)bx * 128 * NCH, NCH,
                       g_w16[z] + (size_t)by * 128 * NCH, NCH,
                       o + (size_t)bx * 128 * NCH + by * 128, NCH, 16);
}

// Stage 2 MERGED: S = q k^T (544 triangular tiles) + vt = Wv x^T (512 tiles).
// grid.x = 1056; all CTAs nch = 16 (fully unrolled).
__global__ __launch_bounds__(256, 2)
void qk_vt(int dummy)
{
    const int idx = blockIdx.x;
    if (idx < 544) {
        const int b = idx / 136;
        const int t = idx - b * 136;
        int by = (int)((sqrtf(8.0f * (float)t + 1.0f) - 1.0f) * 0.5f);
        while ((by + 1) * (by + 2) / 2 <= t) ++by;     // guard fp rounding
        while (by * (by + 1) / 2 > t) --by;
        const int bx = t - by * (by + 1) / 2;          // bx <= by
        mma_core<false, 16>(g_q16 + (size_t)b * NT * NCH + (size_t)by * 128 * NCH, NCH,
                            g_k16 + (size_t)b * NT * NCH + (size_t)bx * 128 * NCH, NCH,
                            g_s + (size_t)b * NT * NT + (size_t)by * 128 * NT
                                + bx * 128, NT, 16);
    } else {
        const int v = idx - 544;           // 0..511
        const int bx = v & 63;             // t-tile (of 8192)
        const int by = v >> 6;             // c-tile (of 1024)
        mma_core<true, 16>(g_w16[2] + (size_t)by * 128 * NCH, NCH,
                           g_x16 + (size_t)bx * 128 * NCH, NCH,
                           g_vt16 + (size_t)by * 128 * NXT + bx * 128, NXT, 16);
    }
}

// Stage 3: causal softmax — warp-per-row, float2 loads / uint32 packed stores.
// grid=(NT/4, NB), 128 threads (4 warps).
__global__ __launch_bounds__(128)
void softmax_causal(float scale)
{
    const int lane = threadIdx.x & 31;
    const int i = blockIdx.x * 4 + (threadIdx.x >> 5);
    const size_t ro = ((size_t)blockIdx.y * NT + i) * NT;
    const float* row = g_s + ro;
    const int len = i + 1;

    float2 v[32];
    float m = -INFINITY;
    #pragma unroll
    for (int k = 0; k < 32; ++k) {
        const int j = 2 * (lane + 32 * k);
        float2 p = *reinterpret_cast<const float2*>(row + j);
        p.x = (j     < len) ? p.x : -INFINITY;
        p.y = (j + 1 < len) ? p.y : -INFINITY;
        v[k] = p;
        m = fmaxf(m, fmaxf(p.x, p.y));
    }
    #pragma unroll
    for (int o = 16; o > 0; o >>= 1) m = fmaxf(m, __shfl_xor_sync(0xffffffffu, m, o));

    float s = 0.0f;
    #pragma unroll
    for (int k = 0; k < 32; ++k) {
        float e0 = __expf((v[k].x - m) * scale);   // -inf -> 0
        float e1 = __expf((v[k].y - m) * scale);
        v[k].x = e0; v[k].y = e1;
        s += e0 + e1;
    }
    #pragma unroll
    for (int o = 16; o > 0; o >>= 1) s += __shfl_xor_sync(0xffffffffu, s, o);
    const float inv = 1.0f / s;

    const int jend = ((i >> 7) + 1) << 7;   // zero-pad to 128-row block boundary
    #pragma unroll
    for (int k = 0; k < 32; ++k) {
        const int j = 2 * (lane + 32 * k);
        if (j < jend)
            *reinterpret_cast<uint32_t*>(g_p16 + ro + j) =
                pack_f16x2(v[k].y * inv, v[k].x * inv);
    }
}

// Stage 4: out = P vt^T, k-extent clipped, GLOBALLY heavy-first:
// grid = (8, NB, 16); z slowest-varying -> by = 15 - z places all heavy
// tiles (every batch) in the first waves.
__global__ __launch_bounds__(256, 2)
void pv_mma(float* __restrict__ out)
{
    const int bx = blockIdx.x, b = blockIdx.y;
    const int by = 15 - (int)blockIdx.z;         // heavy first, all batches
    mma_core<false, 0>(g_p16 + (size_t)b * NT * NT + (size_t)by * 128 * NT, NT,
                       g_vt16 + (size_t)bx * 128 * NXT + (size_t)b * NT, NXT,
                       out + (size_t)b * NT * NCH + (size_t)by * 128 * NCH + bx * 128,
                       NCH, (by + 1) * 2);
}

extern "C" void kernel_launch(void* const* d_in, const int* in_sizes, int n_in,
                              void* d_out, int out_size)
{
    const float* x  = (const float*)d_in[0];
    const float* Wq = (const float*)d_in[1];
    const float* Wk = (const float*)d_in[2];
    const float* Wv = (const float*)d_in[3];
    float* out = (float*)d_out;

    static bool attr_done = false;
    if (!attr_done) {
        cudaFuncSetAttribute(qk_proj, cudaFuncAttributeMaxDynamicSharedMemorySize, SMEM_H);
        cudaFuncSetAttribute(qk_vt,   cudaFuncAttributeMaxDynamicSharedMemorySize, SMEM_H);
        cudaFuncSetAttribute(pv_mma,  cudaFuncAttributeMaxDynamicSharedMemorySize, SMEM_H);
        attr_done = true;
    }

    dim3 blk(256), blk128(128);
    cvt_all<<<2048, blk>>>(x, Wq, Wk, Wv);
    qk_proj<<<dim3(64, 8, 2), blk, SMEM_H>>>(0);
    qk_vt<<<1056, blk, SMEM_H>>>(0);
    softmax_causal<<<dim3(NT / 4, NB), blk128>>>(1.0f / 32.0f);   // 1024^-0.5
    pv_mma<<<dim3(8, NB, 16), blk, SMEM_H>>>(out);
}